// round 14
// baseline (speedup 1.0000x reference)
#include <cuda_runtime.h>
#include <cuda_fp16.h>
#include <math.h>
#include <cstdint>

// ---------------- problem constants ----------------
constexpr int Bz = 64, Hh = 56, Wh = 56, Cc = 128;
constexpr int NH = 4, WS = 7, SS = 3, HID = 512, HD = 32;
constexpr int NW = 64, L = 49;
constexpr int MT = Bz * Hh * Wh;               // 200704 tokens
constexpr float SCALE = 0.17677669529663687f;  // 32^-0.5

// ---------------- scratch ----------------
__device__ __half g_q[(size_t)MT * Cc];      // [win][head][l][hd], q pre-scaled
__device__ __half g_k[(size_t)MT * Cc];
__device__ __half g_v[(size_t)MT * Cc];
__device__ __half g_att[(size_t)MT * Cc];
__device__ __half g_proj[(size_t)MT * Cc];
__device__ __half g_wqkv[384 * 128];
__device__ __half g_wproj[128 * 128];
__device__ __half g_wfc1[512 * 128];
__device__ __half g_wfc2[128 * 512];
__device__ float  g_btab[4 * NH * 64 * 64];  // bias+mask tables per window cat

// ---------------- helpers ----------------
__device__ __forceinline__ uint32_t smem_u32(const void* p) {
    uint32_t a;
    asm("{ .reg .u64 t; cvta.to.shared.u64 t, %1; cvt.u32.u64 %0, t; }" : "=r"(a) : "l"(p));
    return a;
}
__device__ __forceinline__ void ldsm4(uint32_t* r, uint32_t addr) {
    asm volatile("ldmatrix.sync.aligned.m8n8.x4.shared.b16 {%0,%1,%2,%3}, [%4];"
        : "=r"(r[0]), "=r"(r[1]), "=r"(r[2]), "=r"(r[3]) : "r"(addr));
}
__device__ __forceinline__ void mma16816(float* c, const uint32_t* a, const uint32_t* b) {
    asm volatile("mma.sync.aligned.m16n8k16.row.col.f32.f16.f16.f32 "
        "{%0,%1,%2,%3}, {%4,%5,%6,%7}, {%8,%9}, {%0,%1,%2,%3};"
        : "+f"(c[0]), "+f"(c[1]), "+f"(c[2]), "+f"(c[3])
        : "r"(a[0]), "r"(a[1]), "r"(a[2]), "r"(a[3]), "r"(b[0]), "r"(b[1]));
}
__device__ __forceinline__ void cp16(uint32_t s, const void* g) {
    asm volatile("cp.async.cg.shared.global [%0], [%1], 16;" :: "r"(s), "l"(g) : "memory");
}
__device__ __forceinline__ void cp_commit() {
    asm volatile("cp.async.commit_group;" ::: "memory");
}
__device__ __forceinline__ void cp_wait_n(int n) {
    switch (n) {
        case 0: asm volatile("cp.async.wait_group 0;" ::: "memory"); break;
        case 1: asm volatile("cp.async.wait_group 1;" ::: "memory"); break;
        default: asm volatile("cp.async.wait_group 2;" ::: "memory"); break;
    }
}
__device__ __forceinline__ float wsum(float v) {
    #pragma unroll
    for (int o = 16; o; o >>= 1) v += __shfl_xor_sync(0xffffffffu, v, o);
    return v;
}
__device__ __forceinline__ int unshift_idx(int p) {
    int bb = p / (Hh * Wh), pix = p - bb * (Hh * Wh);
    int h = pix / Wh, wc = pix - h * Wh;
    int hs = h - SS; if (hs < 0) hs += Hh;
    int ws = wc - SS; if (ws < 0) ws += Wh;
    return (bb * NW + (hs / WS) * 8 + (ws / WS)) * L + (hs % WS) * WS + (ws % WS);
}

constexpr int LDS = 136;       // padded smem stride (halves): 272B rows

// ---------------- K0: weights fp32 -> fp16 ----------------
__global__ void k_cvt(const float* __restrict__ wq, const float* __restrict__ wp,
                      const float* __restrict__ w1, const float* __restrict__ w2) {
    int i = blockIdx.x * 256 + threadIdx.x;  // 65536 threads
    if (i < 49152) g_wqkv[i] = __float2half_rn(wq[i]);
    if (i < 16384) g_wproj[i] = __float2half_rn(wp[i]);
    g_wfc1[i] = __float2half_rn(w1[i]);
    g_wfc2[i] = __float2half_rn(w2[i]);
}

// ---------------- K0b: precompute bias+mask tables -------------------------
// cat = (window in last row ? 2 : 0) + (window in last col ? 1 : 0)
__global__ void k_btab(const float* __restrict__ rel_bias) {
    const int cat = blockIdx.x >> 2, head = blockIdx.x & 3;
    float* dst = g_btab + (size_t)blockIdx.x * 4096;
    for (int t = threadIdx.x; t < 4096; t += 256) {
        int i = t >> 6, j = t & 63;
        float v;
        if (j >= L) v = -1e30f;
        else if (i >= L) v = 0.f;
        else {
            int rd = i / 7, rm = i - rd * 7;
            int jd = j / 7, jm = j - jd * 7;
            float b = __ldg(rel_bias + ((rd - jd + 6) * 13 + (rm - jm + 6)) * NH + head);
            int whi = cat >> 1, wwi = cat & 1;
            int ri = (whi ? (rd < 4 ? 1 : 2) : 0) * 3 + (wwi ? (rm < 4 ? 1 : 2) : 0);
            int rj = (whi ? (jd < 4 ? 1 : 2) : 0) * 3 + (wwi ? (jm < 4 ? 1 : 2) : 0);
            v = b + (ri != rj ? -100.f : 0.f);
        }
        dst[t] = v;
    }
}

// ---------------- K1: fused LN1+shift + qkv GEMM (round-13 proven) ---------
__global__ void __launch_bounds__(256, 2) k_qkv64(
    const float* __restrict__ x, const float* __restrict__ n1w,
    const float* __restrict__ n1b, const float* __restrict__ bias) {
    extern __shared__ __align__(16) __half sm[];
    __half* sY = sm;
    __half* sW0 = sm + 64 * LDS;
    __half* sW1 = sm + 192 * LDS;
    const uint32_t sYu = smem_u32(sY);
    const uint32_t sWu[2] = {smem_u32(sW0), smem_u32(sW1)};
    const int tid = threadIdx.x, wid = tid >> 5, lane = tid & 31;
    const int wm = wid & 1, wn = wid >> 1;
    const int m0 = blockIdx.x * 64;

    const uint32_t aRow = lane & 15, aCg = (lane >> 4) << 3;
    const uint32_t bRow = (lane & 7) + ((lane >> 4) << 3);
    const uint32_t bCg = ((lane >> 3) & 1) << 3;
    const int lr = lane >> 2, lc = (lane & 3) * 2;

    #pragma unroll
    for (int i = tid; i < 2048; i += 256) {
        int r = i >> 4, g = i & 15;
        cp16(sWu[0] + (r * LDS + g * 8) * 2, g_wqkv + (size_t)r * 128 + g * 8);
    }
    cp_commit();
    #pragma unroll
    for (int i = tid; i < 2048; i += 256) {
        int r = i >> 4, g = i & 15;
        cp16(sWu[1] + (r * LDS + g * 8) * 2, g_wqkv + (size_t)(128 + r) * 128 + g * 8);
    }
    cp_commit();

    {
        const int c = lane * 4;
        const float lw0 = __ldg(n1w + c),     lw1 = __ldg(n1w + c + 1);
        const float lw2 = __ldg(n1w + c + 2), lw3 = __ldg(n1w + c + 3);
        const float lb0 = __ldg(n1b + c),     lb1 = __ldg(n1b + c + 1);
        const float lb2 = __ldg(n1b + c + 2), lb3 = __ldg(n1b + c + 3);
        #pragma unroll
        for (int k = 0; k < 8; k++) {
            const int rloc = wid * 8 + k;
            const int t = m0 + rloc;
            int win = t / L, l = t - win * L;
            int bb = win >> 6, wi = win & 63;
            int wh = wi >> 3, ww = wi & 7;
            int hs = wh * WS + l / WS, ws = ww * WS + l % WS;
            int h0 = hs + SS; if (h0 >= Hh) h0 -= Hh;
            int w0 = ws + SS; if (w0 >= Wh) w0 -= Wh;
            float4 v = ((const float4*)(x + ((size_t)bb * Hh * Wh + h0 * Wh + w0) * Cc))[lane];
            float s  = v.x + v.y + v.z + v.w;
            float s2 = v.x * v.x + v.y * v.y + v.z * v.z + v.w * v.w;
            s = wsum(s); s2 = wsum(s2);
            float mu = s * (1.f / Cc);
            float var = s2 * (1.f / Cc) - mu * mu;
            float rs = rsqrtf(var + 1e-5f);
            __half2* dst = (__half2*)(sY + rloc * LDS + c);
            dst[0] = __floats2half2_rn((v.x - mu) * rs * lw0 + lb0, (v.y - mu) * rs * lw1 + lb1);
            dst[1] = __floats2half2_rn((v.z - mu) * rs * lw2 + lb2, (v.w - mu) * rs * lw3 + lb3);
        }
    }

    #pragma unroll
    for (int nb = 0; nb < 3; nb++) {
        cp_wait_n(nb < 2 ? 1 : 0);
        __syncthreads();
        const uint32_t wbuf = sWu[nb & 1];

        float acc[2][4][4];
        #pragma unroll
        for (int i = 0; i < 2; i++)
            #pragma unroll
            for (int j = 0; j < 4; j++)
                #pragma unroll
                for (int k = 0; k < 4; k++) acc[i][j][k] = 0.f;

        #pragma unroll
        for (int ks = 0; ks < 8; ks++) {
            const int k0 = ks * 16;
            uint32_t afr[2][4];
            #pragma unroll
            for (int mi = 0; mi < 2; mi++)
                ldsm4(afr[mi], sYu + ((wm * 32 + mi * 16 + aRow) * LDS + k0 + aCg) * 2);
            uint32_t bfr[4][2];
            #pragma unroll
            for (int nt = 0; nt < 2; nt++) {
                uint32_t t4[4];
                ldsm4(t4, wbuf + ((wn * 32 + nt * 16 + bRow) * LDS + k0 + bCg) * 2);
                bfr[2 * nt][0] = t4[0]; bfr[2 * nt][1] = t4[1];
                bfr[2 * nt + 1][0] = t4[2]; bfr[2 * nt + 1][1] = t4[3];
            }
            #pragma unroll
            for (int mi = 0; mi < 2; mi++)
                #pragma unroll
                for (int ni = 0; ni < 4; ni++)
                    mma16816(acc[mi][ni], afr[mi], bfr[ni]);
        }

        if (nb == 0) {
            __syncthreads();
            #pragma unroll
            for (int i = tid; i < 2048; i += 256) {
                int r = i >> 4, g = i & 15;
                cp16(sWu[0] + (r * LDS + g * 8) * 2,
                     g_wqkv + (size_t)(256 + r) * 128 + g * 8);
            }
            cp_commit();
        }

        #pragma unroll
        for (int mi = 0; mi < 2; mi++) {
            #pragma unroll
            for (int rr = 0; rr < 2; rr++) {
                const int row = m0 + wm * 32 + mi * 16 + rr * 8 + lr;
                const int win = row / L, lloc = row - win * L;
                #pragma unroll
                for (int ni = 0; ni < 4; ni++) {
                    const int c = wn * 32 + ni * 8 + lc;
                    const int col = nb * 128 + c;
                    float v0 = acc[mi][ni][rr * 2 + 0] + __ldg(bias + col);
                    float v1 = acc[mi][ni][rr * 2 + 1] + __ldg(bias + col + 1);
                    const int head = c >> 5, d = c & 31;
                    __half* dst = (nb == 0 ? g_q : (nb == 1 ? g_k : g_v)) +
                                  ((size_t)(win * NH + head) * L + lloc) * HD + d;
                    if (nb == 0) { v0 *= SCALE; v1 *= SCALE; }
                    *(__half2*)dst = __floats2half2_rn(v0, v1);
                }
            }
        }
    }
}

// ---------------- K2: HMMA GEMM (proj only; round-4 proven) ----------------
template <int NTOT, int KTOT, int EPI>
__global__ void __launch_bounds__(256, 2) k_hmma(
    const __half* __restrict__ A, const __half* __restrict__ Wp,
    const float* __restrict__ bias) {
    extern __shared__ __align__(16) __half sm[];
    __half* sA = sm;
    __half* sW = sm + 128 * LDS;
    const uint32_t sAu = smem_u32(sA), sWu = smem_u32(sW);
    const int tid = threadIdx.x, wid = tid >> 5, lane = tid & 31;
    const int wm = wid & 3, wn = wid >> 2;
    const int m0 = blockIdx.x * 128, n0 = blockIdx.y * 128;

    float acc[2][8][4];
    #pragma unroll
    for (int i = 0; i < 2; i++)
        #pragma unroll
        for (int j = 0; j < 8; j++)
            #pragma unroll
            for (int k = 0; k < 4; k++) acc[i][j][k] = 0.f;

    const uint32_t aRow = lane & 15, aCg = (lane >> 4) << 3;
    const uint32_t bRow = (lane & 7) + ((lane >> 4) << 3);
    const uint32_t bCg = ((lane >> 3) & 1) << 3;

    for (int kb = 0; kb < KTOT / 128; kb++) {
        const __half* Ab = A + (size_t)m0 * KTOT + kb * 128;
        #pragma unroll
        for (int i = tid; i < 128 * 16; i += 256) {
            int r = i >> 4, g = i & 15;
            uint4 v = *(const uint4*)(Ab + (size_t)r * KTOT + g * 8);
            *(uint4*)(sA + r * LDS + g * 8) = v;
        }
        const __half* Wb = Wp + (size_t)n0 * KTOT + kb * 128;
        #pragma unroll
        for (int i = tid; i < 128 * 16; i += 256) {
            int r = i >> 4, g = i & 15;
            uint4 v = *(const uint4*)(Wb + (size_t)r * KTOT + g * 8);
            *(uint4*)(sW + r * LDS + g * 8) = v;
        }
        __syncthreads();

        #pragma unroll
        for (int ks = 0; ks < 8; ks++) {
            const int k0 = ks * 16;
            uint32_t afr[2][4];
            #pragma unroll
            for (int mi = 0; mi < 2; mi++)
                ldsm4(afr[mi], sAu + ((wm * 32 + mi * 16 + aRow) * LDS + k0 + aCg) * 2);
            uint32_t bfr[8][2];
            #pragma unroll
            for (int nb = 0; nb < 4; nb++) {
                uint32_t t4[4];
                ldsm4(t4, sWu + ((wn * 64 + nb * 16 + bRow) * LDS + k0 + bCg) * 2);
                bfr[2 * nb][0] = t4[0]; bfr[2 * nb][1] = t4[1];
                bfr[2 * nb + 1][0] = t4[2]; bfr[2 * nb + 1][1] = t4[3];
            }
            #pragma unroll
            for (int mi = 0; mi < 2; mi++)
                #pragma unroll
                for (int ni = 0; ni < 8; ni++)
                    mma16816(acc[mi][ni], afr[mi], bfr[ni]);
        }
        __syncthreads();
    }

    const int lr = lane >> 2, lc = (lane & 3) * 2;
    #pragma unroll
    for (int mi = 0; mi < 2; mi++) {
        #pragma unroll
        for (int rr = 0; rr < 2; rr++) {
            const int row = m0 + wm * 32 + mi * 16 + rr * 8 + lr;
            #pragma unroll
            for (int ni = 0; ni < 8; ni++) {
                const int col = n0 + wn * 64 + ni * 8 + lc;
                float v0 = acc[mi][ni][rr * 2 + 0] + __ldg(bias + col);
                float v1 = acc[mi][ni][rr * 2 + 1] + __ldg(bias + col + 1);
                *(__half2*)(g_proj + (size_t)row * Cc + col) = __floats2half2_rn(v0, v1);
            }
        }
    }
}

// ---------------- K6: fused tail with register-resident hidden -------------
// grid MT/64, 128 threads (4 warps, each 16 rows x 128 cols), occ-2.
// GEMM1 C-frag (n=128) == GEMM2 A-frag (k=128): GELU applied in registers,
// repacked directly (attention P-trick). No sH smem round trip.
__global__ void __launch_bounds__(128, 2) k_mlpreg(
    const float* __restrict__ x, const __half* __restrict__ proj,
    const __half* __restrict__ W1, const __half* __restrict__ W2,
    const float* __restrict__ b1, const float* __restrict__ b2,
    const float* __restrict__ n2w, const float* __restrict__ n2b,
    float* __restrict__ Out) {
    extern __shared__ __align__(16) __half sm[];
    __half* sY  = sm;                 // 64 x LDS
    __half* sW1 = sm + 64 * LDS;      // 128 x LDS
    __half* sW2 = sm + 192 * LDS;     // 128 x LDS
    const uint32_t sYu = smem_u32(sY);
    const uint32_t sW1u = smem_u32(sW1), sW2u = smem_u32(sW2);
    const int tid = threadIdx.x, wid = tid >> 5, lane = tid & 31;
    const int m0 = blockIdx.x * 64;

    const uint32_t aRow = lane & 15, aCg = (lane >> 4) << 3;
    const uint32_t bRow = (lane & 7) + ((lane >> 4) << 3);
    const uint32_t bCg = ((lane >> 3) & 1) << 3;
    const int lr = lane >> 2, lc = (lane & 3) * 2;

    // prefetch W1[0] (g0), W2[0] (g1)
    #pragma unroll
    for (int i = tid; i < 2048; i += 128) {
        int r = i >> 4, g = i & 15;
        cp16(sW1u + (r * LDS + g * 8) * 2, W1 + (size_t)r * 128 + g * 8);
    }
    cp_commit();
    #pragma unroll
    for (int i = tid; i < 2048; i += 128) {
        int r = i >> 4, g = i & 15;
        cp16(sW2u + (r * LDS + g * 8) * 2, W2 + (size_t)r * 512 + g * 8);
    }
    cp_commit();

    // ---- phase 0: y = LN2(x + unshift(proj)) -> sY (warp = 16 rows) ----
    {
        const int c = lane * 4;
        const float w0 = __ldg(n2w + c),     w1v = __ldg(n2w + c + 1);
        const float w2v = __ldg(n2w + c + 2), w3 = __ldg(n2w + c + 3);
        const float bb0 = __ldg(n2b + c),     bb1 = __ldg(n2b + c + 1);
        const float bb2 = __ldg(n2b + c + 2), bb3 = __ldg(n2b + c + 3);
        #pragma unroll
        for (int k = 0; k < 16; k++) {
            const int rloc = wid * 16 + k;
            const int p = m0 + rloc;
            const int t = unshift_idx(p);
            float4 xv = ((const float4*)(x + (size_t)p * Cc))[lane];
            const __half2* pr = (const __half2*)(proj + (size_t)t * Cc);
            float2 p0 = __half22float2(pr[lane * 2]);
            float2 p1 = __half22float2(pr[lane * 2 + 1]);
            float a0 = xv.x + p0.x, a1 = xv.y + p0.y;
            float a2 = xv.z + p1.x, a3 = xv.w + p1.y;
            float s  = a0 + a1 + a2 + a3;
            float s2 = a0 * a0 + a1 * a1 + a2 * a2 + a3 * a3;
            s = wsum(s); s2 = wsum(s2);
            float mu = s * (1.f / Cc);
            float var = s2 * (1.f / Cc) - mu * mu;
            float rs = rsqrtf(var + 1e-5f);
            __half2* dst = (__half2*)(sY + rloc * LDS + c);
            dst[0] = __floats2half2_rn((a0 - mu) * rs * w0 + bb0, (a1 - mu) * rs * w1v + bb1);
            dst[1] = __floats2half2_rn((a2 - mu) * rs * w2v + bb2, (a3 - mu) * rs * w3 + bb3);
        }
    }

    float acc2[16][4];
    #pragma unroll
    for (int i = 0; i < 16; i++)
        #pragma unroll
        for (int j = 0; j < 4; j++) acc2[i][j] = 0.f;

    #pragma unroll
    for (int nn = 0; nn < 4; nn++) {
        // ---- GEMM1: acc1[16 rows x 128 cols] = y @ W1[nn]^T ----
        cp_wait_n(1);          // W1[nn] arrived (W2[nn] may be pending)
        __syncthreads();       // + sY visible (nn=0) / sW1 safe to read
        float acc1[16][4];
        #pragma unroll
        for (int i = 0; i < 16; i++)
            #pragma unroll
            for (int j = 0; j < 4; j++) acc1[i][j] = 0.f;
        #pragma unroll
        for (int ks = 0; ks < 8; ks++) {
            const int k0 = ks * 16;
            uint32_t afr[4];
            ldsm4(afr, sYu + ((wid * 16 + aRow) * LDS + k0 + aCg) * 2);
            #pragma unroll
            for (int nt = 0; nt < 8; nt++) {
                uint32_t t4[4];
                ldsm4(t4, sW1u + ((nt * 16 + bRow) * LDS + k0 + bCg) * 2);
                { uint32_t b0[2] = {t4[0], t4[1]}; mma16816(acc1[2 * nt], afr, b0); }
                { uint32_t b1r[2] = {t4[2], t4[3]}; mma16816(acc1[2 * nt + 1], afr, b1r); }
            }
        }
        __syncthreads();       // all warps done reading sW1
        if (nn < 3) {          // prefetch W1[nn+1]; overlaps GELU + GEMM2
            #pragma unroll
            for (int i = tid; i < 2048; i += 128) {
                int r = i >> 4, g = i & 15;
                cp16(sW1u + (r * LDS + g * 8) * 2,
                     W1 + (size_t)((nn + 1) * 128 + r) * 128 + g * 8);
            }
            cp_commit();
        }

        // ---- GELU in registers -> A-frags for GEMM2 ----
        uint32_t ph[8][4];
        #pragma unroll
        for (int nt = 0; nt < 16; nt++) {
            const int col = nt * 8 + lc;
            float v0 = acc1[nt][0] + __ldg(b1 + nn * 128 + col);
            float v1 = acc1[nt][1] + __ldg(b1 + nn * 128 + col + 1);
            float v2 = acc1[nt][2] + __ldg(b1 + nn * 128 + col);
            float v3 = acc1[nt][3] + __ldg(b1 + nn * 128 + col + 1);
            float g0 = 0.5f * v0 * (1.0f + erff(v0 * 0.7071067811865475f));
            float g1 = 0.5f * v1 * (1.0f + erff(v1 * 0.7071067811865475f));
            float g2 = 0.5f * v2 * (1.0f + erff(v2 * 0.7071067811865475f));
            float g3 = 0.5f * v3 * (1.0f + erff(v3 * 0.7071067811865475f));
            __half2 h0 = __floats2half2_rn(g0, g1);   // row lr,   k = nt*8+lc..+1
            __half2 h1 = __floats2half2_rn(g2, g3);   // row lr+8
            const int kb = nt >> 1, half = nt & 1;    // a-frag slot
            ph[kb][half * 2 + 0] = *(uint32_t*)&h0;
            ph[kb][half * 2 + 1] = *(uint32_t*)&h1;
        }

        // ---- GEMM2: acc2 += GELU(hid) @ W2[:, nn-block]^T ----
        cp_wait_n(nn < 3 ? 1 : 0);   // W2[nn] arrived (outstanding: W1[nn+1])
        __syncthreads();             // sW2 visible to all
        #pragma unroll
        for (int kb = 0; kb < 8; kb++) {
            const int k0 = kb * 16;
            #pragma unroll
            for (int nt = 0; nt < 8; nt++) {
                uint32_t t4[4];
                ldsm4(t4, sW2u + ((nt * 16 + bRow) * LDS + k0 + bCg) * 2);
                { uint32_t b0[2] = {t4[0], t4[1]}; mma16816(acc2[2 * nt], ph[kb], b0); }
                { uint32_t b1r[2] = {t4[2], t4[3]}; mma16816(acc2[2 * nt + 1], ph[kb], b1r); }
            }
        }
        __syncthreads();       // all warps done reading sW2
        if (nn < 3) {          // prefetch W2[nn+1]; overlaps next GEMM1
            #pragma unroll
            for (int i = tid; i < 2048; i += 128) {
                int r = i >> 4, g = i & 15;
                cp16(sW2u + (r * LDS + g * 8) * 2,
                     W2 + (size_t)r * 512 + (nn + 1) * 128 + g * 8);
            }
            cp_commit();
        }
    }

    // ---- epilogue: + b2 + recomputed x1, fp32 out ----
    #pragma unroll
    for (int rr = 0; rr < 2; rr++) {
        const int row = m0 + wid * 16 + rr * 8 + lr;
        const int t = unshift_idx(row);
        #pragma unroll
        for (int nt = 0; nt < 16; nt++) {
            const int col = nt * 8 + lc;
            float v0 = acc2[nt][rr * 2 + 0] + __ldg(b2 + col);
            float v1 = acc2[nt][rr * 2 + 1] + __ldg(b2 + col + 1);
            const float2 xv = *(const float2*)(x + (size_t)row * Cc + col);
            const float2 pf = __half22float2(*(const __half2*)(proj + (size_t)t * Cc + col));
            float2 ov;
            ov.x = v0 + xv.x + pf.x;
            ov.y = v1 + xv.y + pf.y;
            *(float2*)(Out + (size_t)row * Cc + col) = ov;
        }
    }
}

// ---------------- K3: tensor-core windowed attention, table bias -----------
constexpr int QP = 40;
constexpr int VP = 72;
__global__ void __launch_bounds__(128) k_attn() {
    const int w = blockIdx.x, head = blockIdx.y;
    __shared__ __align__(16) __half qs[64 * QP];
    __shared__ __align__(16) __half ks[64 * QP];
    __shared__ __align__(16) __half vT[32 * VP];
    const int tid = threadIdx.x, warp = tid >> 5, lane = tid & 31;

    const __half* qsrc = g_q + ((size_t)(w * NH + head)) * L * HD;
    const __half* ksrc = g_k + ((size_t)(w * NH + head)) * L * HD;
    const __half* vsrc = g_v + ((size_t)(w * NH + head)) * L * HD;
    const int wi = w & 63;
    const int cat = ((wi >> 3) == 7 ? 2 : 0) + ((wi & 7) == 7 ? 1 : 0);
    const float* tb = g_btab + (size_t)(cat * NH + head) * 4096;

    for (int i = tid; i < (32 * VP) / 8; i += 128)
        ((uint4*)vT)[i] = make_uint4(0, 0, 0, 0);
    for (int i = tid; i < 196; i += 128) {
        int r = i >> 2, g = i & 3;
        *(uint4*)(qs + r * QP + g * 8) = *(const uint4*)(qsrc + r * 32 + g * 8);
        *(uint4*)(ks + r * QP + g * 8) = *(const uint4*)(ksrc + r * 32 + g * 8);
    }
    __syncthreads();
    for (int i = tid; i < 784; i += 128) {
        int j = i >> 4, d = (i & 15) * 2;
        __half2 hv = ((const __half2*)vsrc)[i];
        vT[d * VP + j] = __low2half(hv);
        vT[(d + 1) * VP + j] = __high2half(hv);
    }
    __syncthreads();

    const uint32_t qsu = smem_u32(qs), ksu = smem_u32(ks), vTu = smem_u32(vT);
    const uint32_t aRow = lane & 15, aCg = (lane >> 4) << 3;
    const uint32_t bRow = (lane & 7) + ((lane >> 4) << 3);
    const uint32_t bCg = ((lane >> 3) & 1) << 3;

    float acc[8][4];
    #pragma unroll
    for (int i = 0; i < 8; i++)
        #pragma unroll
        for (int j = 0; j < 4; j++) acc[i][j] = 0.f;

    uint32_t a0[4], a1[4];
    ldsm4(a0, qsu + ((warp * 16 + aRow) * QP + aCg) * 2);
    ldsm4(a1, qsu + ((warp * 16 + aRow) * QP + 16 + aCg) * 2);
    #pragma unroll
    for (int nt = 0; nt < 4; nt++) {
        uint32_t t4[4];
        ldsm4(t4, ksu + ((nt * 16 + bRow) * QP + bCg) * 2);
        { uint32_t b0[2] = {t4[0], t4[1]}, b1[2] = {t4[2], t4[3]};
          mma16816(acc[2 * nt], a0, b0); mma16816(acc[2 * nt + 1], a0, b1); }
        ldsm4(t4, ksu + ((nt * 16 + bRow) * QP + 16 + bCg) * 2);
        { uint32_t b0[2] = {t4[0], t4[1]}, b1[2] = {t4[2], t4[3]};
          mma16816(acc[2 * nt], a1, b0); mma16816(acc[2 * nt + 1], a1, b1); }
    }

    const int lr = lane >> 2, lc2 = (lane & 3) << 1;
    const int i0 = warp * 16 + lr, i1 = i0 + 8;
    const float* tb0 = tb + i0 * 64 + lc2;
    const float* tb1 = tb + i1 * 64 + lc2;

    float mx0 = -1e30f, mx1 = -1e30f;
    #pragma unroll
    for (int nb = 0; nb < 8; nb++) {
        const float2 t0 = __ldg((const float2*)(tb0 + nb * 8));
        const float2 t1 = __ldg((const float2*)(tb1 + nb * 8));
        acc[nb][0] += t0.x; acc[nb][1] += t0.y;
        acc[nb][2] += t1.x; acc[nb][3] += t1.y;
        mx0 = fmaxf(mx0, fmaxf(acc[nb][0], acc[nb][1]));
        mx1 = fmaxf(mx1, fmaxf(acc[nb][2], acc[nb][3]));
    }
    mx0 = fmaxf(mx0, __shfl_xor_sync(0xffffffffu, mx0, 1));
    mx0 = fmaxf(mx0, __shfl_xor_sync(0xffffffffu, mx0, 2));
    mx1 = fmaxf(mx1, __shfl_xor_sync(0xffffffffu, mx1, 1));
    mx1 = fmaxf(mx1, __shfl_xor_sync(0xffffffffu, mx1, 2));
    float sm0 = 0.f, sm1 = 0.f;
    #pragma unroll
    for (int nb = 0; nb < 8; nb++) {
        #pragma unroll
        for (int jj = 0; jj < 2; jj++) {
            float e0 = __expf(acc[nb][jj] - mx0);
            float e1 = __expf(acc[nb][2 + jj] - mx1);
            acc[nb][jj] = e0; acc[nb][2 + jj] = e1;
            sm0 += e0; sm1 += e1;
        }
    }
    sm0 += __shfl_xor_sync(0xffffffffu, sm0, 1);
    sm0 += __shfl_xor_sync(0xffffffffu, sm0, 2);
    sm1 += __shfl_xor_sync(0xffffffffu, sm1, 1);
    sm1 += __shfl_xor_sync(0xffffffffu, sm1, 2);
    const float inv0 = 1.f / sm0, inv1 = 1.f / sm1;

    float o[4][4];
    #pragma unroll
    for (int i = 0; i < 4; i++)
        #pragma unroll
        for (int j = 0; j < 4; j++) o[i][j] = 0.f;
    #pragma unroll
    for (int ks2 = 0; ks2 < 4; ks2++) {
        uint32_t pa[4];
        __half2 h;
        h = __floats2half2_rn(acc[2 * ks2][0], acc[2 * ks2][1]);         pa[0] = *(uint32_t*)&h;
        h = __floats2half2_rn(acc[2 * ks2][2], acc[2 * ks2][3]);         pa[1] = *(uint32_t*)&h;
        h = __floats2half2_rn(acc[2 * ks2 + 1][0], acc[2 * ks2 + 1][1]); pa[2] = *(uint32_t*)&h;
        h = __floats2half2_rn(acc[2 * ks2 + 1][2], acc[2 * ks2 + 1][3]); pa[3] = *(uint32_t*)&h;
        uint32_t t4[4];
        ldsm4(t4, vTu + (bRow * VP + ks2 * 16 + bCg) * 2);
        { uint32_t b0[2] = {t4[0], t4[1]}, b1[2] = {t4[2], t4[3]};
          mma16816(o[0], pa, b0); mma16816(o[1], pa, b1); }
        ldsm4(t4, vTu + ((16 + bRow) * VP + ks2 * 16 + bCg) * 2);
        { uint32_t b0[2] = {t4[0], t4[1]}, b1[2] = {t4[2], t4[3]};
          mma16816(o[2], pa, b0); mma16816(o[3], pa, b1); }
    }

    __half* dst = g_att + (size_t)w * L * Cc + head * HD;
    if (i0 < L) {
        #pragma unroll
        for (int nbo = 0; nbo < 4; nbo++) {
            int col = nbo * 8 + lc2;
            __half2 hv = __floats2half2_rn(o[nbo][0] * inv0, o[nbo][1] * inv0);
            *(__half2*)(dst + (size_t)i0 * Cc + col) = hv;
        }
    }
    if (i1 < L) {
        #pragma unroll
        for (int nbo = 0; nbo < 4; nbo++) {
            int col = nbo * 8 + lc2;
            __half2 hv = __floats2half2_rn(o[nbo][2] * inv1, o[nbo][3] * inv1);
            *(__half2*)(dst + (size_t)i1 * Cc + col) = hv;
        }
    }
}

// ---------------- launch ----------------
extern "C" void kernel_launch(void* const* d_in, const int* in_sizes, int n_in,
                              void* d_out, int out_size) {
    const float* x      = (const float*)d_in[0];
    const float* n1w    = (const float*)d_in[1];
    const float* n1b    = (const float*)d_in[2];
    const float* qkv_w  = (const float*)d_in[3];
    const float* qkv_b  = (const float*)d_in[4];
    const float* proj_w = (const float*)d_in[5];
    const float* proj_b = (const float*)d_in[6];
    const float* rel_b  = (const float*)d_in[7];
    const float* n2w    = (const float*)d_in[8];
    const float* n2b    = (const float*)d_in[9];
    const float* fc1_w  = (const float*)d_in[10];
    const float* fc1_b  = (const float*)d_in[11];
    const float* fc2_w  = (const float*)d_in[12];
    const float* fc2_b  = (const float*)d_in[13];
    float* out = (float*)d_out;

    __half *p_att, *p_proj, *p_wproj, *p_wfc1, *p_wfc2;
    cudaGetSymbolAddress((void**)&p_att,  g_att);
    cudaGetSymbolAddress((void**)&p_proj, g_proj);
    cudaGetSymbolAddress((void**)&p_wproj, g_wproj);
    cudaGetSymbolAddress((void**)&p_wfc1, g_wfc1);
    cudaGetSymbolAddress((void**)&p_wfc2, g_wfc2);

    constexpr int SMB = 2 * 128 * LDS * 2;      // 69632 B (k_hmma)
    constexpr int SMB_Q = 320 * LDS * 2;        // 87040 B (k_qkv64, occ 2)
    constexpr int SMB_M = 320 * LDS * 2;        // 87040 B (k_mlpreg, occ 2)
    cudaFuncSetAttribute(k_qkv64, cudaFuncAttributeMaxDynamicSharedMemorySize, SMB_Q);
    cudaFuncSetAttribute(k_hmma<128, 128, 0>, cudaFuncAttributeMaxDynamicSharedMemorySize, SMB);
    cudaFuncSetAttribute(k_mlpreg, cudaFuncAttributeMaxDynamicSharedMemorySize, SMB_M);

    const int GM = MT / 128;  // 1568 M-tiles

    k_cvt<<<256, 256>>>(qkv_w, proj_w, fc1_w, fc2_w);
    k_btab<<<16, 256>>>(rel_b);
    k_qkv64<<<MT / 64, 256, SMB_Q>>>(x, n1w, n1b, qkv_b);
    k_attn<<<dim3(Bz * NW, NH), 128>>>();
    k_hmma<128, 128, 0><<<dim3(GM, 1), 256, SMB>>>(p_att, p_wproj, proj_b);
    k_mlpreg<<<MT / 64, 128, SMB_M>>>(x, p_proj, p_wfc1, p_wfc2, fc1_b, fc2_b, n2w, n2b, out);
}

// round 16
// speedup vs baseline: 1.3711x; 1.3711x over previous
#include <cuda_runtime.h>
#include <cuda_fp16.h>
#include <math.h>
#include <cstdint>

// ---------------- problem constants ----------------
constexpr int Bz = 64, Hh = 56, Wh = 56, Cc = 128;
constexpr int NH = 4, WS = 7, SS = 3, HID = 512, HD = 32;
constexpr int NW = 64, L = 49;
constexpr int MT = Bz * Hh * Wh;               // 200704 tokens
constexpr float SCALE = 0.17677669529663687f;  // 32^-0.5

// ---------------- scratch ----------------
__device__ __half g_q[(size_t)MT * Cc];      // [win][head][l][hd], q pre-scaled
__device__ __half g_k[(size_t)MT * Cc];
__device__ __half g_v[(size_t)MT * Cc];
__device__ __half g_att[(size_t)MT * Cc];
__device__ __half g_proj[(size_t)MT * Cc];
__device__ __half g_wqkv[384 * 128];
__device__ __half g_wproj[128 * 128];
__device__ __half g_wfc1[512 * 128];
__device__ __half g_wfc2[128 * 512];

// ---------------- helpers ----------------
__device__ __forceinline__ uint32_t smem_u32(const void* p) {
    uint32_t a;
    asm("{ .reg .u64 t; cvta.to.shared.u64 t, %1; cvt.u32.u64 %0, t; }" : "=r"(a) : "l"(p));
    return a;
}
__device__ __forceinline__ void ldsm4(uint32_t* r, uint32_t addr) {
    asm volatile("ldmatrix.sync.aligned.m8n8.x4.shared.b16 {%0,%1,%2,%3}, [%4];"
        : "=r"(r[0]), "=r"(r[1]), "=r"(r[2]), "=r"(r[3]) : "r"(addr));
}
__device__ __forceinline__ void mma16816(float* c, const uint32_t* a, const uint32_t* b) {
    asm volatile("mma.sync.aligned.m16n8k16.row.col.f32.f16.f16.f32 "
        "{%0,%1,%2,%3}, {%4,%5,%6,%7}, {%8,%9}, {%0,%1,%2,%3};"
        : "+f"(c[0]), "+f"(c[1]), "+f"(c[2]), "+f"(c[3])
        : "r"(a[0]), "r"(a[1]), "r"(a[2]), "r"(a[3]), "r"(b[0]), "r"(b[1]));
}
__device__ __forceinline__ void cp16(uint32_t s, const void* g) {
    asm volatile("cp.async.cg.shared.global [%0], [%1], 16;" :: "r"(s), "l"(g) : "memory");
}
__device__ __forceinline__ void cp_commit() {
    asm volatile("cp.async.commit_group;" ::: "memory");
}
__device__ __forceinline__ void cp_wait_n(int n) {
    switch (n) {
        case 0: asm volatile("cp.async.wait_group 0;" ::: "memory"); break;
        case 1: asm volatile("cp.async.wait_group 1;" ::: "memory"); break;
        default: asm volatile("cp.async.wait_group 2;" ::: "memory"); break;
    }
}
__device__ __forceinline__ float wsum(float v) {
    #pragma unroll
    for (int o = 16; o; o >>= 1) v += __shfl_xor_sync(0xffffffffu, v, o);
    return v;
}
__device__ __forceinline__ int unshift_idx(int p) {
    int bb = p / (Hh * Wh), pix = p - bb * (Hh * Wh);
    int h = pix / Wh, wc = pix - h * Wh;
    int hs = h - SS; if (hs < 0) hs += Hh;
    int ws = wc - SS; if (ws < 0) ws += Wh;
    return (bb * NW + (hs / WS) * 8 + (ws / WS)) * L + (hs % WS) * WS + (ws % WS);
}

constexpr int LDS = 136;       // padded smem stride (halves): 272B rows

// ---------------- K0: weights fp32 -> fp16 ----------------
__global__ void k_cvt(const float* __restrict__ wq, const float* __restrict__ wp,
                      const float* __restrict__ w1, const float* __restrict__ w2) {
    int i = blockIdx.x * 256 + threadIdx.x;  // 65536 threads
    if (i < 49152) g_wqkv[i] = __float2half_rn(wq[i]);
    if (i < 16384) g_wproj[i] = __float2half_rn(wp[i]);
    g_wfc1[i] = __float2half_rn(w1[i]);
    g_wfc2[i] = __float2half_rn(w2[i]);
}

// ---------------- K1: fused LN1+shift + qkv GEMM (round-13 proven) ---------
__global__ void __launch_bounds__(256, 2) k_qkv64(
    const float* __restrict__ x, const float* __restrict__ n1w,
    const float* __restrict__ n1b, const float* __restrict__ bias) {
    extern __shared__ __align__(16) __half sm[];
    __half* sY = sm;                          // 64 x LDS
    __half* sW0 = sm + 64 * LDS;              // 128 x LDS
    __half* sW1 = sm + 192 * LDS;             // 128 x LDS
    const uint32_t sYu = smem_u32(sY);
    const uint32_t sWu[2] = {smem_u32(sW0), smem_u32(sW1)};
    const int tid = threadIdx.x, wid = tid >> 5, lane = tid & 31;
    const int wm = wid & 1, wn = wid >> 1;    // 2m x 4n warp grid
    const int m0 = blockIdx.x * 64;

    const uint32_t aRow = lane & 15, aCg = (lane >> 4) << 3;
    const uint32_t bRow = (lane & 7) + ((lane >> 4) << 3);
    const uint32_t bCg = ((lane >> 3) & 1) << 3;
    const int lr = lane >> 2, lc = (lane & 3) * 2;

    #pragma unroll
    for (int i = tid; i < 2048; i += 256) {
        int r = i >> 4, g = i & 15;
        cp16(sWu[0] + (r * LDS + g * 8) * 2, g_wqkv + (size_t)r * 128 + g * 8);
    }
    cp_commit();
    #pragma unroll
    for (int i = tid; i < 2048; i += 256) {
        int r = i >> 4, g = i & 15;
        cp16(sWu[1] + (r * LDS + g * 8) * 2, g_wqkv + (size_t)(128 + r) * 128 + g * 8);
    }
    cp_commit();

    // phase 0: LN1 + cyclic shift gather -> sY (computed once)
    {
        const int c = lane * 4;
        const float lw0 = __ldg(n1w + c),     lw1 = __ldg(n1w + c + 1);
        const float lw2 = __ldg(n1w + c + 2), lw3 = __ldg(n1w + c + 3);
        const float lb0 = __ldg(n1b + c),     lb1 = __ldg(n1b + c + 1);
        const float lb2 = __ldg(n1b + c + 2), lb3 = __ldg(n1b + c + 3);
        #pragma unroll
        for (int k = 0; k < 8; k++) {
            const int rloc = wid * 8 + k;
            const int t = m0 + rloc;
            int win = t / L, l = t - win * L;
            int bb = win >> 6, wi = win & 63;
            int wh = wi >> 3, ww = wi & 7;
            int hs = wh * WS + l / WS, ws = ww * WS + l % WS;
            int h0 = hs + SS; if (h0 >= Hh) h0 -= Hh;
            int w0 = ws + SS; if (w0 >= Wh) w0 -= Wh;
            float4 v = ((const float4*)(x + ((size_t)bb * Hh * Wh + h0 * Wh + w0) * Cc))[lane];
            float s  = v.x + v.y + v.z + v.w;
            float s2 = v.x * v.x + v.y * v.y + v.z * v.z + v.w * v.w;
            s = wsum(s); s2 = wsum(s2);
            float mu = s * (1.f / Cc);
            float var = s2 * (1.f / Cc) - mu * mu;
            float rs = rsqrtf(var + 1e-5f);
            __half2* dst = (__half2*)(sY + rloc * LDS + c);
            dst[0] = __floats2half2_rn((v.x - mu) * rs * lw0 + lb0, (v.y - mu) * rs * lw1 + lb1);
            dst[1] = __floats2half2_rn((v.z - mu) * rs * lw2 + lb2, (v.w - mu) * rs * lw3 + lb3);
        }
    }

    #pragma unroll
    for (int nb = 0; nb < 3; nb++) {
        cp_wait_n(nb < 2 ? 1 : 0);
        __syncthreads();
        const uint32_t wbuf = sWu[nb & 1];

        float acc[2][4][4];
        #pragma unroll
        for (int i = 0; i < 2; i++)
            #pragma unroll
            for (int j = 0; j < 4; j++)
                #pragma unroll
                for (int k = 0; k < 4; k++) acc[i][j][k] = 0.f;

        #pragma unroll
        for (int ks = 0; ks < 8; ks++) {
            const int k0 = ks * 16;
            uint32_t afr[2][4];
            #pragma unroll
            for (int mi = 0; mi < 2; mi++)
                ldsm4(afr[mi], sYu + ((wm * 32 + mi * 16 + aRow) * LDS + k0 + aCg) * 2);
            uint32_t bfr[4][2];
            #pragma unroll
            for (int nt = 0; nt < 2; nt++) {
                uint32_t t4[4];
                ldsm4(t4, wbuf + ((wn * 32 + nt * 16 + bRow) * LDS + k0 + bCg) * 2);
                bfr[2 * nt][0] = t4[0]; bfr[2 * nt][1] = t4[1];
                bfr[2 * nt + 1][0] = t4[2]; bfr[2 * nt + 1][1] = t4[3];
            }
            #pragma unroll
            for (int mi = 0; mi < 2; mi++)
                #pragma unroll
                for (int ni = 0; ni < 4; ni++)
                    mma16816(acc[mi][ni], afr[mi], bfr[ni]);
        }

        if (nb == 0) {
            __syncthreads();
            #pragma unroll
            for (int i = tid; i < 2048; i += 256) {
                int r = i >> 4, g = i & 15;
                cp16(sWu[0] + (r * LDS + g * 8) * 2,
                     g_wqkv + (size_t)(256 + r) * 128 + g * 8);
            }
            cp_commit();
        }

        #pragma unroll
        for (int mi = 0; mi < 2; mi++) {
            #pragma unroll
            for (int rr = 0; rr < 2; rr++) {
                const int row = m0 + wm * 32 + mi * 16 + rr * 8 + lr;
                const int win = row / L, lloc = row - win * L;
                #pragma unroll
                for (int ni = 0; ni < 4; ni++) {
                    const int c = wn * 32 + ni * 8 + lc;
                    const int col = nb * 128 + c;
                    float v0 = acc[mi][ni][rr * 2 + 0] + __ldg(bias + col);
                    float v1 = acc[mi][ni][rr * 2 + 1] + __ldg(bias + col + 1);
                    const int head = c >> 5, d = c & 31;
                    __half* dst = (nb == 0 ? g_q : (nb == 1 ? g_k : g_v)) +
                                  ((size_t)(win * NH + head) * L + lloc) * HD + d;
                    if (nb == 0) { v0 *= SCALE; v1 *= SCALE; }
                    *(__half2*)dst = __floats2half2_rn(v0, v1);
                }
            }
        }
    }
}

// ---------------- K2: proj GEMM, 64-row tiles, cp.async-staged -------------
// grid MT/64, 256 threads (8 warps, 2m x 4n, 32x32 warp tiles), occ-2.
// Single 128-K GEMM: 64x128x128; A (attn out) + W staged via cp.async.
__global__ void __launch_bounds__(256, 2) k_proj64(
    const __half* __restrict__ A, const __half* __restrict__ Wp,
    const float* __restrict__ bias) {
    extern __shared__ __align__(16) __half sm[];
    __half* sA = sm;                 // 64 x LDS
    __half* sW = sm + 64 * LDS;      // 128 x LDS
    const uint32_t sAu = smem_u32(sA), sWu = smem_u32(sW);
    const int tid = threadIdx.x, wid = tid >> 5, lane = tid & 31;
    const int wm = wid & 1, wn = wid >> 1;
    const int m0 = blockIdx.x * 64;

    const uint32_t aRow = lane & 15, aCg = (lane >> 4) << 3;
    const uint32_t bRow = (lane & 7) + ((lane >> 4) << 3);
    const uint32_t bCg = ((lane >> 3) & 1) << 3;
    const int lr = lane >> 2, lc = (lane & 3) * 2;

    // stage A (64x128) + W (128x128) in one cp.async group
    #pragma unroll
    for (int i = tid; i < 1024; i += 256) {
        int r = i >> 4, g = i & 15;
        cp16(sAu + (r * LDS + g * 8) * 2, A + (size_t)(m0 + r) * 128 + g * 8);
    }
    #pragma unroll
    for (int i = tid; i < 2048; i += 256) {
        int r = i >> 4, g = i & 15;
        cp16(sWu + (r * LDS + g * 8) * 2, Wp + (size_t)r * 128 + g * 8);
    }
    cp_commit();
    cp_wait_n(0);
    __syncthreads();

    float acc[2][4][4];
    #pragma unroll
    for (int i = 0; i < 2; i++)
        #pragma unroll
        for (int j = 0; j < 4; j++)
            #pragma unroll
            for (int k = 0; k < 4; k++) acc[i][j][k] = 0.f;

    #pragma unroll
    for (int ks = 0; ks < 8; ks++) {
        const int k0 = ks * 16;
        uint32_t afr[2][4];
        #pragma unroll
        for (int mi = 0; mi < 2; mi++)
            ldsm4(afr[mi], sAu + ((wm * 32 + mi * 16 + aRow) * LDS + k0 + aCg) * 2);
        uint32_t bfr[4][2];
        #pragma unroll
        for (int nt = 0; nt < 2; nt++) {
            uint32_t t4[4];
            ldsm4(t4, sWu + ((wn * 32 + nt * 16 + bRow) * LDS + k0 + bCg) * 2);
            bfr[2 * nt][0] = t4[0]; bfr[2 * nt][1] = t4[1];
            bfr[2 * nt + 1][0] = t4[2]; bfr[2 * nt + 1][1] = t4[3];
        }
        #pragma unroll
        for (int mi = 0; mi < 2; mi++)
            #pragma unroll
            for (int ni = 0; ni < 4; ni++)
                mma16816(acc[mi][ni], afr[mi], bfr[ni]);
    }

    #pragma unroll
    for (int mi = 0; mi < 2; mi++) {
        #pragma unroll
        for (int rr = 0; rr < 2; rr++) {
            const int row = m0 + wm * 32 + mi * 16 + rr * 8 + lr;
            #pragma unroll
            for (int ni = 0; ni < 4; ni++) {
                const int col = wn * 32 + ni * 8 + lc;
                float v0 = acc[mi][ni][rr * 2 + 0] + __ldg(bias + col);
                float v1 = acc[mi][ni][rr * 2 + 1] + __ldg(bias + col + 1);
                *(__half2*)(g_proj + (size_t)row * Cc + col) = __floats2half2_rn(v0, v1);
            }
        }
    }
}

// ---------------- K6: fused tail, 64-row tiles, occ-2 (round-12 proven) ----
__global__ void __launch_bounds__(256, 2) k_mlp64(
    const float* __restrict__ x, const __half* __restrict__ proj,
    const __half* __restrict__ W1, const __half* __restrict__ W2,
    const float* __restrict__ b1, const float* __restrict__ b2,
    const float* __restrict__ n2w, const float* __restrict__ n2b,
    float* __restrict__ Out) {
    extern __shared__ __align__(16) __half sm[];
    __half* sY  = sm;
    __half* sH  = sm + 64 * LDS;
    __half* sX  = sm + 128 * LDS;
    __half* sW2 = sm + 256 * LDS;
    const uint32_t sYu = smem_u32(sY), sHu = smem_u32(sH);
    const uint32_t sXu = smem_u32(sX), sW2u = smem_u32(sW2);
    const int tid = threadIdx.x, wid = tid >> 5, lane = tid & 31;
    const int wm = wid & 1, wn = wid >> 1;
    const int m0 = blockIdx.x * 64;

    const uint32_t aRow = lane & 15, aCg = (lane >> 4) << 3;
    const uint32_t bRow = (lane & 7) + ((lane >> 4) << 3);
    const uint32_t bCg = ((lane >> 3) & 1) << 3;
    const int lr = lane >> 2, lc = (lane & 3) * 2;

    #pragma unroll
    for (int i = tid; i < 2048; i += 256) {
        int r = i >> 4, g = i & 15;
        cp16(sXu + (r * LDS + g * 8) * 2, W1 + (size_t)r * 128 + g * 8);
    }
    cp_commit();
    #pragma unroll
    for (int i = tid; i < 2048; i += 256) {
        int r = i >> 4, g = i & 15;
        cp16(sW2u + (r * LDS + g * 8) * 2, W2 + (size_t)r * 512 + g * 8);
    }
    cp_commit();

    {
        const int c = lane * 4;
        const float w0 = __ldg(n2w + c),     w1v = __ldg(n2w + c + 1);
        const float w2v = __ldg(n2w + c + 2), w3 = __ldg(n2w + c + 3);
        const float bb0 = __ldg(n2b + c),     bb1 = __ldg(n2b + c + 1);
        const float bb2 = __ldg(n2b + c + 2), bb3 = __ldg(n2b + c + 3);
        #pragma unroll
        for (int k = 0; k < 8; k++) {
            const int rloc = wid * 8 + k;
            const int p = m0 + rloc;
            const int t = unshift_idx(p);
            float4 xv = ((const float4*)(x + (size_t)p * Cc))[lane];
            const __half2* pr = (const __half2*)(proj + (size_t)t * Cc);
            float2 p0 = __half22float2(pr[lane * 2]);
            float2 p1 = __half22float2(pr[lane * 2 + 1]);
            float a0 = xv.x + p0.x, a1 = xv.y + p0.y;
            float a2 = xv.z + p1.x, a3 = xv.w + p1.y;
            float s  = a0 + a1 + a2 + a3;
            float s2 = a0 * a0 + a1 * a1 + a2 * a2 + a3 * a3;
            s = wsum(s); s2 = wsum(s2);
            float mu = s * (1.f / Cc);
            float var = s2 * (1.f / Cc) - mu * mu;
            float rs = rsqrtf(var + 1e-5f);
            __half2* dst = (__half2*)(sY + rloc * LDS + c);
            dst[0] = __floats2half2_rn((a0 - mu) * rs * w0 + bb0, (a1 - mu) * rs * w1v + bb1);
            dst[1] = __floats2half2_rn((a2 - mu) * rs * w2v + bb2, (a3 - mu) * rs * w3 + bb3);
        }
    }

    float acc2[2][4][4];
    #pragma unroll
    for (int i = 0; i < 2; i++)
        #pragma unroll
        for (int j = 0; j < 4; j++)
            #pragma unroll
            for (int k = 0; k < 4; k++) acc2[i][j][k] = 0.f;

    #pragma unroll
    for (int nn = 0; nn < 4; nn++) {
        cp_wait_n(1);
        __syncthreads();
        float acc1[2][4][4];
        #pragma unroll
        for (int i = 0; i < 2; i++)
            #pragma unroll
            for (int j = 0; j < 4; j++)
                #pragma unroll
                for (int k = 0; k < 4; k++) acc1[i][j][k] = 0.f;
        #pragma unroll
        for (int ks = 0; ks < 8; ks++) {
            const int k0 = ks * 16;
            uint32_t afr[2][4];
            #pragma unroll
            for (int mi = 0; mi < 2; mi++)
                ldsm4(afr[mi], sYu + ((wm * 32 + mi * 16 + aRow) * LDS + k0 + aCg) * 2);
            uint32_t bfr[4][2];
            #pragma unroll
            for (int nb = 0; nb < 2; nb++) {
                uint32_t t4[4];
                ldsm4(t4, sXu + ((wn * 32 + nb * 16 + bRow) * LDS + k0 + bCg) * 2);
                bfr[2 * nb][0] = t4[0]; bfr[2 * nb][1] = t4[1];
                bfr[2 * nb + 1][0] = t4[2]; bfr[2 * nb + 1][1] = t4[3];
            }
            #pragma unroll
            for (int mi = 0; mi < 2; mi++)
                #pragma unroll
                for (int ni = 0; ni < 4; ni++)
                    mma16816(acc1[mi][ni], afr[mi], bfr[ni]);
        }
        __syncthreads();
        if (nn < 3) {
            #pragma unroll
            for (int i = tid; i < 2048; i += 256) {
                int r = i >> 4, g = i & 15;
                cp16(sXu + (r * LDS + g * 8) * 2,
                     W1 + (size_t)((nn + 1) * 128 + r) * 128 + g * 8);
            }
            cp_commit();
        }

        #pragma unroll
        for (int mi = 0; mi < 2; mi++) {
            #pragma unroll
            for (int rr = 0; rr < 2; rr++) {
                const int row = wm * 32 + mi * 16 + rr * 8 + lr;
                #pragma unroll
                for (int ni = 0; ni < 4; ni++) {
                    const int col = wn * 32 + ni * 8 + lc;
                    float v0 = acc1[mi][ni][rr * 2 + 0] + __ldg(b1 + nn * 128 + col);
                    float v1 = acc1[mi][ni][rr * 2 + 1] + __ldg(b1 + nn * 128 + col + 1);
                    float g0 = 0.5f * v0 * (1.0f + erff(v0 * 0.7071067811865475f));
                    float g1 = 0.5f * v1 * (1.0f + erff(v1 * 0.7071067811865475f));
                    *(__half2*)(sH + row * LDS + col) = __floats2half2_rn(g0, g1);
                }
            }
        }

        cp_wait_n(nn < 3 ? 1 : 0);
        __syncthreads();
        #pragma unroll
        for (int ks = 0; ks < 8; ks++) {
            const int k0 = ks * 16;
            uint32_t afr[2][4];
            #pragma unroll
            for (int mi = 0; mi < 2; mi++)
                ldsm4(afr[mi], sHu + ((wm * 32 + mi * 16 + aRow) * LDS + k0 + aCg) * 2);
            uint32_t bfr[4][2];
            #pragma unroll
            for (int nb = 0; nb < 2; nb++) {
                uint32_t t4[4];
                ldsm4(t4, sW2u + ((wn * 32 + nb * 16 + bRow) * LDS + k0 + bCg) * 2);
                bfr[2 * nb][0] = t4[0]; bfr[2 * nb][1] = t4[1];
                bfr[2 * nb + 1][0] = t4[2]; bfr[2 * nb + 1][1] = t4[3];
            }
            #pragma unroll
            for (int mi = 0; mi < 2; mi++)
                #pragma unroll
                for (int ni = 0; ni < 4; ni++)
                    mma16816(acc2[mi][ni], afr[mi], bfr[ni]);
        }
        __syncthreads();
        if (nn < 3) {
            #pragma unroll
            for (int i = tid; i < 2048; i += 256) {
                int r = i >> 4, g = i & 15;
                cp16(sW2u + (r * LDS + g * 8) * 2,
                     W2 + (size_t)r * 512 + (nn + 1) * 128 + g * 8);
            }
            cp_commit();
        }
    }

    #pragma unroll
    for (int mi = 0; mi < 2; mi++) {
        #pragma unroll
        for (int rr = 0; rr < 2; rr++) {
            const int row = m0 + wm * 32 + mi * 16 + rr * 8 + lr;
            const int t = unshift_idx(row);
            #pragma unroll
            for (int ni = 0; ni < 4; ni++) {
                const int col = wn * 32 + ni * 8 + lc;
                float v0 = acc2[mi][ni][rr * 2 + 0] + __ldg(b2 + col);
                float v1 = acc2[mi][ni][rr * 2 + 1] + __ldg(b2 + col + 1);
                const float2 xv = *(const float2*)(x + (size_t)row * Cc + col);
                const float2 pf = __half22float2(*(const __half2*)(proj + (size_t)t * Cc + col));
                float2 ov;
                ov.x = v0 + xv.x + pf.x;
                ov.y = v1 + xv.y + pf.y;
                *(float2*)(Out + (size_t)row * Cc + col) = ov;
            }
        }
    }
}

// ---------------- K3: tensor-core windowed attention (round-4 proven) ------
constexpr int QP = 40;
constexpr int VP = 72;
__global__ void __launch_bounds__(128) k_attn(const float* __restrict__ rel_bias) {
    const int w = blockIdx.x, head = blockIdx.y;
    __shared__ __align__(16) __half qs[64 * QP];
    __shared__ __align__(16) __half ks[64 * QP];
    __shared__ __align__(16) __half vT[32 * VP];
    __shared__ float bias_s[256];
    __shared__ int pk[64];
    const int tid = threadIdx.x, warp = tid >> 5, lane = tid & 31;

    const __half* qsrc = g_q + ((size_t)(w * NH + head)) * L * HD;
    const __half* ksrc = g_k + ((size_t)(w * NH + head)) * L * HD;
    const __half* vsrc = g_v + ((size_t)(w * NH + head)) * L * HD;

    for (int i = tid; i < (32 * VP) / 8; i += 128)
        ((uint4*)vT)[i] = make_uint4(0, 0, 0, 0);
    for (int i = tid; i < 256; i += 128)
        bias_s[i] = (i < 169) ? __ldg(rel_bias + i * 4 + head) : 0.f;
    if (tid < 64) {
        int t = tid;
        int rd = t / 7, rm = t - rd * 7;
        int c1 = (rd + 6) * 13 + rm + 6;
        int c2 = rd * 13 + rm;
        int wi = w & 63, wh = wi >> 3, ww = wi & 7;
        int hs = wh * WS + rd, wsp = ww * WS + rm;
        int rh = hs < (Hh - WS) ? 0 : (hs < (Hh - SS) ? 1 : 2);
        int rw = wsp < (Wh - WS) ? 0 : (wsp < (Wh - SS) ? 1 : 2);
        pk[t] = (c1 << 16) | (c2 << 8) | (rh * 3 + rw);
    }
    for (int i = tid; i < 196; i += 128) {
        int r = i >> 2, g = i & 3;
        *(uint4*)(qs + r * QP + g * 8) = *(const uint4*)(qsrc + r * 32 + g * 8);
        *(uint4*)(ks + r * QP + g * 8) = *(const uint4*)(ksrc + r * 32 + g * 8);
    }
    __syncthreads();
    for (int i = tid; i < 784; i += 128) {
        int j = i >> 4, d = (i & 15) * 2;
        __half2 hv = ((const __half2*)vsrc)[i];
        vT[d * VP + j] = __low2half(hv);
        vT[(d + 1) * VP + j] = __high2half(hv);
    }
    __syncthreads();

    const uint32_t qsu = smem_u32(qs), ksu = smem_u32(ks), vTu = smem_u32(vT);
    const uint32_t aRow = lane & 15, aCg = (lane >> 4) << 3;
    const uint32_t bRow = (lane & 7) + ((lane >> 4) << 3);
    const uint32_t bCg = ((lane >> 3) & 1) << 3;

    float acc[8][4];
    #pragma unroll
    for (int i = 0; i < 8; i++)
        #pragma unroll
        for (int j = 0; j < 4; j++) acc[i][j] = 0.f;

    uint32_t a0[4], a1[4];
    ldsm4(a0, qsu + ((warp * 16 + aRow) * QP + aCg) * 2);
    ldsm4(a1, qsu + ((warp * 16 + aRow) * QP + 16 + aCg) * 2);
    #pragma unroll
    for (int nt = 0; nt < 4; nt++) {
        uint32_t t4[4];
        ldsm4(t4, ksu + ((nt * 16 + bRow) * QP + bCg) * 2);
        { uint32_t b0[2] = {t4[0], t4[1]}, b1[2] = {t4[2], t4[3]};
          mma16816(acc[2 * nt], a0, b0); mma16816(acc[2 * nt + 1], a0, b1); }
        ldsm4(t4, ksu + ((nt * 16 + bRow) * QP + 16 + bCg) * 2);
        { uint32_t b0[2] = {t4[0], t4[1]}, b1[2] = {t4[2], t4[3]};
          mma16816(acc[2 * nt], a1, b0); mma16816(acc[2 * nt + 1], a1, b1); }
    }

    const int lr = lane >> 2, lc2 = (lane & 3) << 1;
    const int i0 = warp * 16 + lr, i1 = i0 + 8;
    const int pki0 = pk[i0], pki1 = pk[i1];
    const int c1_0 = pki0 >> 16, rg0 = pki0 & 255;
    const int c1_1 = pki1 >> 16, rg1 = pki1 & 255;

    float mx0 = -1e30f, mx1 = -1e30f;
    #pragma unroll
    for (int nb = 0; nb < 8; nb++) {
        #pragma unroll
        for (int jj = 0; jj < 2; jj++) {
            int j = nb * 8 + lc2 + jj;
            int pj = pk[j];
            int c2j = (pj >> 8) & 255, rgj = pj & 255;
            bool jlt = j < L;
            float b0 = bias_s[(c1_0 - c2j) & 255];
            float b1 = bias_s[(c1_1 - c2j) & 255];
            float s0 = acc[nb][jj] + b0 + ((rg0 == rgj) ? 0.f : -100.f);
            float s1 = acc[nb][2 + jj] + b1 + ((rg1 == rgj) ? 0.f : -100.f);
            s0 = jlt ? s0 : -1e30f;
            s1 = jlt ? s1 : -1e30f;
            acc[nb][jj] = s0; acc[nb][2 + jj] = s1;
            mx0 = fmaxf(mx0, s0); mx1 = fmaxf(mx1, s1);
        }
    }
    mx0 = fmaxf(mx0, __shfl_xor_sync(0xffffffffu, mx0, 1));
    mx0 = fmaxf(mx0, __shfl_xor_sync(0xffffffffu, mx0, 2));
    mx1 = fmaxf(mx1, __shfl_xor_sync(0xffffffffu, mx1, 1));
    mx1 = fmaxf(mx1, __shfl_xor_sync(0xffffffffu, mx1, 2));
    float sm0 = 0.f, sm1 = 0.f;
    #pragma unroll
    for (int nb = 0; nb < 8; nb++) {
        #pragma unroll
        for (int jj = 0; jj < 2; jj++) {
            float e0 = __expf(acc[nb][jj] - mx0);
            float e1 = __expf(acc[nb][2 + jj] - mx1);
            acc[nb][jj] = e0; acc[nb][2 + jj] = e1;
            sm0 += e0; sm1 += e1;
        }
    }
    sm0 += __shfl_xor_sync(0xffffffffu, sm0, 1);
    sm0 += __shfl_xor_sync(0xffffffffu, sm0, 2);
    sm1 += __shfl_xor_sync(0xffffffffu, sm1, 1);
    sm1 += __shfl_xor_sync(0xffffffffu, sm1, 2);
    const float inv0 = 1.f / sm0, inv1 = 1.f / sm1;

    float o[4][4];
    #pragma unroll
    for (int i = 0; i < 4; i++)
        #pragma unroll
        for (int j = 0; j < 4; j++) o[i][j] = 0.f;
    #pragma unroll
    for (int ks2 = 0; ks2 < 4; ks2++) {
        uint32_t pa[4];
        __half2 h;
        h = __floats2half2_rn(acc[2 * ks2][0], acc[2 * ks2][1]);         pa[0] = *(uint32_t*)&h;
        h = __floats2half2_rn(acc[2 * ks2][2], acc[2 * ks2][3]);         pa[1] = *(uint32_t*)&h;
        h = __floats2half2_rn(acc[2 * ks2 + 1][0], acc[2 * ks2 + 1][1]); pa[2] = *(uint32_t*)&h;
        h = __floats2half2_rn(acc[2 * ks2 + 1][2], acc[2 * ks2 + 1][3]); pa[3] = *(uint32_t*)&h;
        uint32_t t4[4];
        ldsm4(t4, vTu + (bRow * VP + ks2 * 16 + bCg) * 2);
        { uint32_t b0[2] = {t4[0], t4[1]}, b1[2] = {t4[2], t4[3]};
          mma16816(o[0], pa, b0); mma16816(o[1], pa, b1); }
        ldsm4(t4, vTu + ((16 + bRow) * VP + ks2 * 16 + bCg) * 2);
        { uint32_t b0[2] = {t4[0], t4[1]}, b1[2] = {t4[2], t4[3]};
          mma16816(o[2], pa, b0); mma16816(o[3], pa, b1); }
    }

    __half* dst = g_att + (size_t)w * L * Cc + head * HD;
    if (i0 < L) {
        #pragma unroll
        for (int nbo = 0; nbo < 4; nbo++) {
            int col = nbo * 8 + lc2;
            __half2 hv = __floats2half2_rn(o[nbo][0] * inv0, o[nbo][1] * inv0);
            *(__half2*)(dst + (size_t)i0 * Cc + col) = hv;
        }
    }
    if (i1 < L) {
        #pragma unroll
        for (int nbo = 0; nbo < 4; nbo++) {
            int col = nbo * 8 + lc2;
            __half2 hv = __floats2half2_rn(o[nbo][2] * inv1, o[nbo][3] * inv1);
            *(__half2*)(dst + (size_t)i1 * Cc + col) = hv;
        }
    }
}

// ---------------- launch ----------------
extern "C" void kernel_launch(void* const* d_in, const int* in_sizes, int n_in,
                              void* d_out, int out_size) {
    const float* x      = (const float*)d_in[0];
    const float* n1w    = (const float*)d_in[1];
    const float* n1b    = (const float*)d_in[2];
    const float* qkv_w  = (const float*)d_in[3];
    const float* qkv_b  = (const float*)d_in[4];
    const float* proj_w = (const float*)d_in[5];
    const float* proj_b = (const float*)d_in[6];
    const float* rel_b  = (const float*)d_in[7];
    const float* n2w    = (const float*)d_in[8];
    const float* n2b    = (const float*)d_in[9];
    const float* fc1_w  = (const float*)d_in[10];
    const float* fc1_b  = (const float*)d_in[11];
    const float* fc2_w  = (const float*)d_in[12];
    const float* fc2_b  = (const float*)d_in[13];
    float* out = (float*)d_out;

    __half *p_att, *p_proj, *p_wproj, *p_wfc1, *p_wfc2;
    cudaGetSymbolAddress((void**)&p_att,  g_att);
    cudaGetSymbolAddress((void**)&p_proj, g_proj);
    cudaGetSymbolAddress((void**)&p_wproj, g_wproj);
    cudaGetSymbolAddress((void**)&p_wfc1, g_wfc1);
    cudaGetSymbolAddress((void**)&p_wfc2, g_wfc2);

    constexpr int SMB_Q = 320 * LDS * 2;        // 87040 B (k_qkv64, occ 2)
    constexpr int SMB_P = 192 * LDS * 2;        // 52224 B (k_proj64, occ 2+)
    constexpr int SMB_M = 384 * LDS * 2;        // 104448 B (k_mlp64, occ 2)
    cudaFuncSetAttribute(k_qkv64, cudaFuncAttributeMaxDynamicSharedMemorySize, SMB_Q);
    cudaFuncSetAttribute(k_proj64, cudaFuncAttributeMaxDynamicSharedMemorySize, SMB_P);
    cudaFuncSetAttribute(k_mlp64, cudaFuncAttributeMaxDynamicSharedMemorySize, SMB_M);

    k_cvt<<<256, 256>>>(qkv_w, proj_w, fc1_w, fc2_w);
    k_qkv64<<<MT / 64, 256, SMB_Q>>>(x, n1w, n1b, qkv_b);
    k_attn<<<dim3(Bz * NW, NH), 128>>>(rel_b);
    k_proj64<<<MT / 64, 256, SMB_P>>>(p_att, p_wproj, proj_b);
    k_mlp64<<<MT / 64, 256, SMB_M>>>(x, p_proj, p_wfc1, p_wfc2, fc1_b, fc2_b, n2w, n2b, out);
}

// round 17
// speedup vs baseline: 1.4711x; 1.0730x over previous
#include <cuda_runtime.h>
#include <cuda_fp16.h>
#include <math.h>
#include <cstdint>

// ---------------- problem constants ----------------
constexpr int Bz = 64, Hh = 56, Wh = 56, Cc = 128;
constexpr int NH = 4, WS = 7, SS = 3, HID = 512, HD = 32;
constexpr int NW = 64, L = 49;
constexpr int MT = Bz * Hh * Wh;               // 200704 tokens
constexpr float SCALE = 0.17677669529663687f;  // 32^-0.5

// ---------------- scratch ----------------
__device__ __half g_q[(size_t)MT * Cc];      // [win][head][l][hd], q pre-scaled
__device__ __half g_k[(size_t)MT * Cc];
__device__ __half g_v[(size_t)MT * Cc];
__device__ __half g_att[(size_t)MT * Cc];
__device__ __half g_proj[(size_t)MT * Cc];
__device__ __half g_wqkv[384 * 128];
__device__ __half g_wproj[128 * 128];
__device__ __half g_wfc1[512 * 128];
__device__ __half g_wfc2[128 * 512];

// ---------------- helpers ----------------
__device__ __forceinline__ uint32_t smem_u32(const void* p) {
    uint32_t a;
    asm("{ .reg .u64 t; cvta.to.shared.u64 t, %1; cvt.u32.u64 %0, t; }" : "=r"(a) : "l"(p));
    return a;
}
__device__ __forceinline__ void ldsm4(uint32_t* r, uint32_t addr) {
    asm volatile("ldmatrix.sync.aligned.m8n8.x4.shared.b16 {%0,%1,%2,%3}, [%4];"
        : "=r"(r[0]), "=r"(r[1]), "=r"(r[2]), "=r"(r[3]) : "r"(addr));
}
__device__ __forceinline__ void ldsm4t(uint32_t* r, uint32_t addr) {
    asm volatile("ldmatrix.sync.aligned.m8n8.x4.trans.shared.b16 {%0,%1,%2,%3}, [%4];"
        : "=r"(r[0]), "=r"(r[1]), "=r"(r[2]), "=r"(r[3]) : "r"(addr));
}
__device__ __forceinline__ void mma16816(float* c, const uint32_t* a, const uint32_t* b) {
    asm volatile("mma.sync.aligned.m16n8k16.row.col.f32.f16.f16.f32 "
        "{%0,%1,%2,%3}, {%4,%5,%6,%7}, {%8,%9}, {%0,%1,%2,%3};"
        : "+f"(c[0]), "+f"(c[1]), "+f"(c[2]), "+f"(c[3])
        : "r"(a[0]), "r"(a[1]), "r"(a[2]), "r"(a[3]), "r"(b[0]), "r"(b[1]));
}
__device__ __forceinline__ void cp16(uint32_t s, const void* g) {
    asm volatile("cp.async.cg.shared.global [%0], [%1], 16;" :: "r"(s), "l"(g) : "memory");
}
__device__ __forceinline__ void cp_commit() {
    asm volatile("cp.async.commit_group;" ::: "memory");
}
__device__ __forceinline__ void cp_wait_n(int n) {
    switch (n) {
        case 0: asm volatile("cp.async.wait_group 0;" ::: "memory"); break;
        case 1: asm volatile("cp.async.wait_group 1;" ::: "memory"); break;
        default: asm volatile("cp.async.wait_group 2;" ::: "memory"); break;
    }
}
__device__ __forceinline__ float wsum(float v) {
    #pragma unroll
    for (int o = 16; o; o >>= 1) v += __shfl_xor_sync(0xffffffffu, v, o);
    return v;
}
__device__ __forceinline__ int unshift_idx(int p) {
    int bb = p / (Hh * Wh), pix = p - bb * (Hh * Wh);
    int h = pix / Wh, wc = pix - h * Wh;
    int hs = h - SS; if (hs < 0) hs += Hh;
    int ws = wc - SS; if (ws < 0) ws += Wh;
    return (bb * NW + (hs / WS) * 8 + (ws / WS)) * L + (hs % WS) * WS + (ws % WS);
}

constexpr int LDS = 136;       // padded smem stride (halves): 272B rows

// ---------------- K0: weights fp32 -> fp16 ----------------
__global__ void k_cvt(const float* __restrict__ wq, const float* __restrict__ wp,
                      const float* __restrict__ w1, const float* __restrict__ w2) {
    int i = blockIdx.x * 256 + threadIdx.x;  // 65536 threads
    if (i < 49152) g_wqkv[i] = __float2half_rn(wq[i]);
    if (i < 16384) g_wproj[i] = __float2half_rn(wp[i]);
    g_wfc1[i] = __float2half_rn(w1[i]);
    g_wfc2[i] = __float2half_rn(w2[i]);
}

// ---------------- K1: fused LN1+shift + qkv GEMM (round-13 proven) ---------
__global__ void __launch_bounds__(256, 2) k_qkv64(
    const float* __restrict__ x, const float* __restrict__ n1w,
    const float* __restrict__ n1b, const float* __restrict__ bias) {
    extern __shared__ __align__(16) __half sm[];
    __half* sY = sm;                          // 64 x LDS
    __half* sW0 = sm + 64 * LDS;              // 128 x LDS
    __half* sW1 = sm + 192 * LDS;             // 128 x LDS
    const uint32_t sYu = smem_u32(sY);
    const uint32_t sWu[2] = {smem_u32(sW0), smem_u32(sW1)};
    const int tid = threadIdx.x, wid = tid >> 5, lane = tid & 31;
    const int wm = wid & 1, wn = wid >> 1;    // 2m x 4n warp grid
    const int m0 = blockIdx.x * 64;

    const uint32_t aRow = lane & 15, aCg = (lane >> 4) << 3;
    const uint32_t bRow = (lane & 7) + ((lane >> 4) << 3);
    const uint32_t bCg = ((lane >> 3) & 1) << 3;
    const int lr = lane >> 2, lc = (lane & 3) * 2;

    #pragma unroll
    for (int i = tid; i < 2048; i += 256) {
        int r = i >> 4, g = i & 15;
        cp16(sWu[0] + (r * LDS + g * 8) * 2, g_wqkv + (size_t)r * 128 + g * 8);
    }
    cp_commit();
    #pragma unroll
    for (int i = tid; i < 2048; i += 256) {
        int r = i >> 4, g = i & 15;
        cp16(sWu[1] + (r * LDS + g * 8) * 2, g_wqkv + (size_t)(128 + r) * 128 + g * 8);
    }
    cp_commit();

    // phase 0: LN1 + cyclic shift gather -> sY (computed once)
    {
        const int c = lane * 4;
        const float lw0 = __ldg(n1w + c),     lw1 = __ldg(n1w + c + 1);
        const float lw2 = __ldg(n1w + c + 2), lw3 = __ldg(n1w + c + 3);
        const float lb0 = __ldg(n1b + c),     lb1 = __ldg(n1b + c + 1);
        const float lb2 = __ldg(n1b + c + 2), lb3 = __ldg(n1b + c + 3);
        #pragma unroll
        for (int k = 0; k < 8; k++) {
            const int rloc = wid * 8 + k;
            const int t = m0 + rloc;
            int win = t / L, l = t - win * L;
            int bb = win >> 6, wi = win & 63;
            int wh = wi >> 3, ww = wi & 7;
            int hs = wh * WS + l / WS, ws = ww * WS + l % WS;
            int h0 = hs + SS; if (h0 >= Hh) h0 -= Hh;
            int w0 = ws + SS; if (w0 >= Wh) w0 -= Wh;
            float4 v = ((const float4*)(x + ((size_t)bb * Hh * Wh + h0 * Wh + w0) * Cc))[lane];
            float s  = v.x + v.y + v.z + v.w;
            float s2 = v.x * v.x + v.y * v.y + v.z * v.z + v.w * v.w;
            s = wsum(s); s2 = wsum(s2);
            float mu = s * (1.f / Cc);
            float var = s2 * (1.f / Cc) - mu * mu;
            float rs = rsqrtf(var + 1e-5f);
            __half2* dst = (__half2*)(sY + rloc * LDS + c);
            dst[0] = __floats2half2_rn((v.x - mu) * rs * lw0 + lb0, (v.y - mu) * rs * lw1 + lb1);
            dst[1] = __floats2half2_rn((v.z - mu) * rs * lw2 + lb2, (v.w - mu) * rs * lw3 + lb3);
        }
    }

    #pragma unroll
    for (int nb = 0; nb < 3; nb++) {
        cp_wait_n(nb < 2 ? 1 : 0);
        __syncthreads();
        const uint32_t wbuf = sWu[nb & 1];

        float acc[2][4][4];
        #pragma unroll
        for (int i = 0; i < 2; i++)
            #pragma unroll
            for (int j = 0; j < 4; j++)
                #pragma unroll
                for (int k = 0; k < 4; k++) acc[i][j][k] = 0.f;

        #pragma unroll
        for (int ks = 0; ks < 8; ks++) {
            const int k0 = ks * 16;
            uint32_t afr[2][4];
            #pragma unroll
            for (int mi = 0; mi < 2; mi++)
                ldsm4(afr[mi], sYu + ((wm * 32 + mi * 16 + aRow) * LDS + k0 + aCg) * 2);
            uint32_t bfr[4][2];
            #pragma unroll
            for (int nt = 0; nt < 2; nt++) {
                uint32_t t4[4];
                ldsm4(t4, wbuf + ((wn * 32 + nt * 16 + bRow) * LDS + k0 + bCg) * 2);
                bfr[2 * nt][0] = t4[0]; bfr[2 * nt][1] = t4[1];
                bfr[2 * nt + 1][0] = t4[2]; bfr[2 * nt + 1][1] = t4[3];
            }
            #pragma unroll
            for (int mi = 0; mi < 2; mi++)
                #pragma unroll
                for (int ni = 0; ni < 4; ni++)
                    mma16816(acc[mi][ni], afr[mi], bfr[ni]);
        }

        if (nb == 0) {
            __syncthreads();
            #pragma unroll
            for (int i = tid; i < 2048; i += 256) {
                int r = i >> 4, g = i & 15;
                cp16(sWu[0] + (r * LDS + g * 8) * 2,
                     g_wqkv + (size_t)(256 + r) * 128 + g * 8);
            }
            cp_commit();
        }

        #pragma unroll
        for (int mi = 0; mi < 2; mi++) {
            #pragma unroll
            for (int rr = 0; rr < 2; rr++) {
                const int row = m0 + wm * 32 + mi * 16 + rr * 8 + lr;
                const int win = row / L, lloc = row - win * L;
                #pragma unroll
                for (int ni = 0; ni < 4; ni++) {
                    const int c = wn * 32 + ni * 8 + lc;
                    const int col = nb * 128 + c;
                    float v0 = acc[mi][ni][rr * 2 + 0] + __ldg(bias + col);
                    float v1 = acc[mi][ni][rr * 2 + 1] + __ldg(bias + col + 1);
                    const int head = c >> 5, d = c & 31;
                    __half* dst = (nb == 0 ? g_q : (nb == 1 ? g_k : g_v)) +
                                  ((size_t)(win * NH + head) * L + lloc) * HD + d;
                    if (nb == 0) { v0 *= SCALE; v1 *= SCALE; }
                    *(__half2*)dst = __floats2half2_rn(v0, v1);
                }
            }
        }
    }
}

// ---------------- K2: HMMA GEMM (proj only; round-4/13 proven) -------------
template <int NTOT, int KTOT, int EPI>
__global__ void __launch_bounds__(256, 2) k_hmma(
    const __half* __restrict__ A, const __half* __restrict__ Wp,
    const float* __restrict__ bias) {
    extern __shared__ __align__(16) __half sm[];
    __half* sA = sm;
    __half* sW = sm + 128 * LDS;
    const uint32_t sAu = smem_u32(sA), sWu = smem_u32(sW);
    const int tid = threadIdx.x, wid = tid >> 5, lane = tid & 31;
    const int wm = wid & 3, wn = wid >> 2;
    const int m0 = blockIdx.x * 128, n0 = blockIdx.y * 128;

    float acc[2][8][4];
    #pragma unroll
    for (int i = 0; i < 2; i++)
        #pragma unroll
        for (int j = 0; j < 8; j++)
            #pragma unroll
            for (int k = 0; k < 4; k++) acc[i][j][k] = 0.f;

    const uint32_t aRow = lane & 15, aCg = (lane >> 4) << 3;
    const uint32_t bRow = (lane & 7) + ((lane >> 4) << 3);
    const uint32_t bCg = ((lane >> 3) & 1) << 3;

    for (int kb = 0; kb < KTOT / 128; kb++) {
        const __half* Ab = A + (size_t)m0 * KTOT + kb * 128;
        #pragma unroll
        for (int i = tid; i < 128 * 16; i += 256) {
            int r = i >> 4, g = i & 15;
            uint4 v = *(const uint4*)(Ab + (size_t)r * KTOT + g * 8);
            *(uint4*)(sA + r * LDS + g * 8) = v;
        }
        const __half* Wb = Wp + (size_t)n0 * KTOT + kb * 128;
        #pragma unroll
        for (int i = tid; i < 128 * 16; i += 256) {
            int r = i >> 4, g = i & 15;
            uint4 v = *(const uint4*)(Wb + (size_t)r * KTOT + g * 8);
            *(uint4*)(sW + r * LDS + g * 8) = v;
        }
        __syncthreads();

        #pragma unroll
        for (int ks = 0; ks < 8; ks++) {
            const int k0 = ks * 16;
            uint32_t afr[2][4];
            #pragma unroll
            for (int mi = 0; mi < 2; mi++)
                ldsm4(afr[mi], sAu + ((wm * 32 + mi * 16 + aRow) * LDS + k0 + aCg) * 2);
            uint32_t bfr[8][2];
            #pragma unroll
            for (int nb = 0; nb < 4; nb++) {
                uint32_t t4[4];
                ldsm4(t4, sWu + ((wn * 64 + nb * 16 + bRow) * LDS + k0 + bCg) * 2);
                bfr[2 * nb][0] = t4[0]; bfr[2 * nb][1] = t4[1];
                bfr[2 * nb + 1][0] = t4[2]; bfr[2 * nb + 1][1] = t4[3];
            }
            #pragma unroll
            for (int mi = 0; mi < 2; mi++)
                #pragma unroll
                for (int ni = 0; ni < 8; ni++)
                    mma16816(acc[mi][ni], afr[mi], bfr[ni]);
        }
        __syncthreads();
    }

    const int lr = lane >> 2, lc = (lane & 3) * 2;
    #pragma unroll
    for (int mi = 0; mi < 2; mi++) {
        #pragma unroll
        for (int rr = 0; rr < 2; rr++) {
            const int row = m0 + wm * 32 + mi * 16 + rr * 8 + lr;
            #pragma unroll
            for (int ni = 0; ni < 8; ni++) {
                const int col = n0 + wn * 64 + ni * 8 + lc;
                float v0 = acc[mi][ni][rr * 2 + 0] + __ldg(bias + col);
                float v1 = acc[mi][ni][rr * 2 + 1] + __ldg(bias + col + 1);
                *(__half2*)(g_proj + (size_t)row * Cc + col) = __floats2half2_rn(v0, v1);
            }
        }
    }
}

// ---------------- K6: fused tail, 64-row tiles, occ-2 (round-12 proven) ----
__global__ void __launch_bounds__(256, 2) k_mlp64(
    const float* __restrict__ x, const __half* __restrict__ proj,
    const __half* __restrict__ W1, const __half* __restrict__ W2,
    const float* __restrict__ b1, const float* __restrict__ b2,
    const float* __restrict__ n2w, const float* __restrict__ n2b,
    float* __restrict__ Out) {
    extern __shared__ __align__(16) __half sm[];
    __half* sY  = sm;
    __half* sH  = sm + 64 * LDS;
    __half* sX  = sm + 128 * LDS;
    __half* sW2 = sm + 256 * LDS;
    const uint32_t sYu = smem_u32(sY), sHu = smem_u32(sH);
    const uint32_t sXu = smem_u32(sX), sW2u = smem_u32(sW2);
    const int tid = threadIdx.x, wid = tid >> 5, lane = tid & 31;
    const int wm = wid & 1, wn = wid >> 1;
    const int m0 = blockIdx.x * 64;

    const uint32_t aRow = lane & 15, aCg = (lane >> 4) << 3;
    const uint32_t bRow = (lane & 7) + ((lane >> 4) << 3);
    const uint32_t bCg = ((lane >> 3) & 1) << 3;
    const int lr = lane >> 2, lc = (lane & 3) * 2;

    #pragma unroll
    for (int i = tid; i < 2048; i += 256) {
        int r = i >> 4, g = i & 15;
        cp16(sXu + (r * LDS + g * 8) * 2, W1 + (size_t)r * 128 + g * 8);
    }
    cp_commit();
    #pragma unroll
    for (int i = tid; i < 2048; i += 256) {
        int r = i >> 4, g = i & 15;
        cp16(sW2u + (r * LDS + g * 8) * 2, W2 + (size_t)r * 512 + g * 8);
    }
    cp_commit();

    {
        const int c = lane * 4;
        const float w0 = __ldg(n2w + c),     w1v = __ldg(n2w + c + 1);
        const float w2v = __ldg(n2w + c + 2), w3 = __ldg(n2w + c + 3);
        const float bb0 = __ldg(n2b + c),     bb1 = __ldg(n2b + c + 1);
        const float bb2 = __ldg(n2b + c + 2), bb3 = __ldg(n2b + c + 3);
        #pragma unroll
        for (int k = 0; k < 8; k++) {
            const int rloc = wid * 8 + k;
            const int p = m0 + rloc;
            const int t = unshift_idx(p);
            float4 xv = ((const float4*)(x + (size_t)p * Cc))[lane];
            const __half2* pr = (const __half2*)(proj + (size_t)t * Cc);
            float2 p0 = __half22float2(pr[lane * 2]);
            float2 p1 = __half22float2(pr[lane * 2 + 1]);
            float a0 = xv.x + p0.x, a1 = xv.y + p0.y;
            float a2 = xv.z + p1.x, a3 = xv.w + p1.y;
            float s  = a0 + a1 + a2 + a3;
            float s2 = a0 * a0 + a1 * a1 + a2 * a2 + a3 * a3;
            s = wsum(s); s2 = wsum(s2);
            float mu = s * (1.f / Cc);
            float var = s2 * (1.f / Cc) - mu * mu;
            float rs = rsqrtf(var + 1e-5f);
            __half2* dst = (__half2*)(sY + rloc * LDS + c);
            dst[0] = __floats2half2_rn((a0 - mu) * rs * w0 + bb0, (a1 - mu) * rs * w1v + bb1);
            dst[1] = __floats2half2_rn((a2 - mu) * rs * w2v + bb2, (a3 - mu) * rs * w3 + bb3);
        }
    }

    float acc2[2][4][4];
    #pragma unroll
    for (int i = 0; i < 2; i++)
        #pragma unroll
        for (int j = 0; j < 4; j++)
            #pragma unroll
            for (int k = 0; k < 4; k++) acc2[i][j][k] = 0.f;

    #pragma unroll
    for (int nn = 0; nn < 4; nn++) {
        cp_wait_n(1);
        __syncthreads();
        float acc1[2][4][4];
        #pragma unroll
        for (int i = 0; i < 2; i++)
            #pragma unroll
            for (int j = 0; j < 4; j++)
                #pragma unroll
                for (int k = 0; k < 4; k++) acc1[i][j][k] = 0.f;
        #pragma unroll
        for (int ks = 0; ks < 8; ks++) {
            const int k0 = ks * 16;
            uint32_t afr[2][4];
            #pragma unroll
            for (int mi = 0; mi < 2; mi++)
                ldsm4(afr[mi], sYu + ((wm * 32 + mi * 16 + aRow) * LDS + k0 + aCg) * 2);
            uint32_t bfr[4][2];
            #pragma unroll
            for (int nb = 0; nb < 2; nb++) {
                uint32_t t4[4];
                ldsm4(t4, sXu + ((wn * 32 + nb * 16 + bRow) * LDS + k0 + bCg) * 2);
                bfr[2 * nb][0] = t4[0]; bfr[2 * nb][1] = t4[1];
                bfr[2 * nb + 1][0] = t4[2]; bfr[2 * nb + 1][1] = t4[3];
            }
            #pragma unroll
            for (int mi = 0; mi < 2; mi++)
                #pragma unroll
                for (int ni = 0; ni < 4; ni++)
                    mma16816(acc1[mi][ni], afr[mi], bfr[ni]);
        }
        __syncthreads();
        if (nn < 3) {
            #pragma unroll
            for (int i = tid; i < 2048; i += 256) {
                int r = i >> 4, g = i & 15;
                cp16(sXu + (r * LDS + g * 8) * 2,
                     W1 + (size_t)((nn + 1) * 128 + r) * 128 + g * 8);
            }
            cp_commit();
        }

        #pragma unroll
        for (int mi = 0; mi < 2; mi++) {
            #pragma unroll
            for (int rr = 0; rr < 2; rr++) {
                const int row = wm * 32 + mi * 16 + rr * 8 + lr;
                #pragma unroll
                for (int ni = 0; ni < 4; ni++) {
                    const int col = wn * 32 + ni * 8 + lc;
                    float v0 = acc1[mi][ni][rr * 2 + 0] + __ldg(b1 + nn * 128 + col);
                    float v1 = acc1[mi][ni][rr * 2 + 1] + __ldg(b1 + nn * 128 + col + 1);
                    float g0 = 0.5f * v0 * (1.0f + erff(v0 * 0.7071067811865475f));
                    float g1 = 0.5f * v1 * (1.0f + erff(v1 * 0.7071067811865475f));
                    *(__half2*)(sH + row * LDS + col) = __floats2half2_rn(g0, g1);
                }
            }
        }

        cp_wait_n(nn < 3 ? 1 : 0);
        __syncthreads();
        #pragma unroll
        for (int ks = 0; ks < 8; ks++) {
            const int k0 = ks * 16;
            uint32_t afr[2][4];
            #pragma unroll
            for (int mi = 0; mi < 2; mi++)
                ldsm4(afr[mi], sHu + ((wm * 32 + mi * 16 + aRow) * LDS + k0 + aCg) * 2);
            uint32_t bfr[4][2];
            #pragma unroll
            for (int nb = 0; nb < 2; nb++) {
                uint32_t t4[4];
                ldsm4(t4, sW2u + ((wn * 32 + nb * 16 + bRow) * LDS + k0 + bCg) * 2);
                bfr[2 * nb][0] = t4[0]; bfr[2 * nb][1] = t4[1];
                bfr[2 * nb + 1][0] = t4[2]; bfr[2 * nb + 1][1] = t4[3];
            }
            #pragma unroll
            for (int mi = 0; mi < 2; mi++)
                #pragma unroll
                for (int ni = 0; ni < 4; ni++)
                    mma16816(acc2[mi][ni], afr[mi], bfr[ni]);
        }
        __syncthreads();
        if (nn < 3) {
            #pragma unroll
            for (int i = tid; i < 2048; i += 256) {
                int r = i >> 4, g = i & 15;
                cp16(sW2u + (r * LDS + g * 8) * 2,
                     W2 + (size_t)r * 512 + (nn + 1) * 128 + g * 8);
            }
            cp_commit();
        }
    }

    #pragma unroll
    for (int mi = 0; mi < 2; mi++) {
        #pragma unroll
        for (int rr = 0; rr < 2; rr++) {
            const int row = m0 + wm * 32 + mi * 16 + rr * 8 + lr;
            const int t = unshift_idx(row);
            #pragma unroll
            for (int ni = 0; ni < 4; ni++) {
                const int col = wn * 32 + ni * 8 + lc;
                float v0 = acc2[mi][ni][rr * 2 + 0] + __ldg(b2 + col);
                float v1 = acc2[mi][ni][rr * 2 + 1] + __ldg(b2 + col + 1);
                const float2 xv = *(const float2*)(x + (size_t)row * Cc + col);
                const float2 pf = __half22float2(*(const __half2*)(proj + (size_t)t * Cc + col));
                float2 ov;
                ov.x = v0 + xv.x + pf.x;
                ov.y = v1 + xv.y + pf.y;
                *(float2*)(Out + (size_t)row * Cc + col) = ov;
            }
        }
    }
}

// ---------------- K3: windowed attention, V via ldmatrix.trans -------------
constexpr int QP = 40;   // q/k/v smem row stride (halves): 80B rows
__global__ void __launch_bounds__(128) k_attn(const float* __restrict__ rel_bias) {
    const int w = blockIdx.x, head = blockIdx.y;
    __shared__ __align__(16) __half qs[64 * QP];
    __shared__ __align__(16) __half ks[64 * QP];
    __shared__ __align__(16) __half vs[64 * QP];   // row-major V; rows 49-63 zeroed
    __shared__ float bias_s[256];
    __shared__ int pk[64];
    const int tid = threadIdx.x, warp = tid >> 5, lane = tid & 31;

    const __half* qsrc = g_q + ((size_t)(w * NH + head)) * L * HD;
    const __half* ksrc = g_k + ((size_t)(w * NH + head)) * L * HD;
    const __half* vsrc = g_v + ((size_t)(w * NH + head)) * L * HD;

    // zero padded V rows (j >= 49): halves [1960, 2560) = 75 uint4
    for (int i = tid; i < 75; i += 128)
        ((uint4*)(vs + 49 * QP))[i] = make_uint4(0, 0, 0, 0);
    for (int i = tid; i < 256; i += 128)
        bias_s[i] = (i < 169) ? __ldg(rel_bias + i * 4 + head) : 0.f;
    if (tid < 64) {
        int t = tid;
        int rd = t / 7, rm = t - rd * 7;
        int c1 = (rd + 6) * 13 + rm + 6;
        int c2 = rd * 13 + rm;
        int wi = w & 63, wh = wi >> 3, ww = wi & 7;
        int hs = wh * WS + rd, wsp = ww * WS + rm;
        int rh = hs < (Hh - WS) ? 0 : (hs < (Hh - SS) ? 1 : 2);
        int rw = wsp < (Wh - WS) ? 0 : (wsp < (Wh - SS) ? 1 : 2);
        pk[t] = (c1 << 16) | (c2 << 8) | (rh * 3 + rw);
    }
    for (int i = tid; i < 196; i += 128) {   // 49 rows x 4 uint4 each
        int r = i >> 2, g = i & 3;
        *(uint4*)(qs + r * QP + g * 8) = *(const uint4*)(qsrc + r * 32 + g * 8);
        *(uint4*)(ks + r * QP + g * 8) = *(const uint4*)(ksrc + r * 32 + g * 8);
        *(uint4*)(vs + r * QP + g * 8) = *(const uint4*)(vsrc + r * 32 + g * 8);
    }
    __syncthreads();

    const uint32_t qsu = smem_u32(qs), ksu = smem_u32(ks), vsu = smem_u32(vs);
    const uint32_t aRow = lane & 15, aCg = (lane >> 4) << 3;
    const uint32_t bRow = (lane & 7) + ((lane >> 4) << 3);
    const uint32_t bCg = ((lane >> 3) & 1) << 3;

    float acc[8][4];
    #pragma unroll
    for (int i = 0; i < 8; i++)
        #pragma unroll
        for (int j = 0; j < 4; j++) acc[i][j] = 0.f;

    uint32_t a0[4], a1[4];
    ldsm4(a0, qsu + ((warp * 16 + aRow) * QP + aCg) * 2);
    ldsm4(a1, qsu + ((warp * 16 + aRow) * QP + 16 + aCg) * 2);
    #pragma unroll
    for (int nt = 0; nt < 4; nt++) {
        uint32_t t4[4];
        ldsm4(t4, ksu + ((nt * 16 + bRow) * QP + bCg) * 2);
        { uint32_t b0[2] = {t4[0], t4[1]}, b1[2] = {t4[2], t4[3]};
          mma16816(acc[2 * nt], a0, b0); mma16816(acc[2 * nt + 1], a0, b1); }
        ldsm4(t4, ksu + ((nt * 16 + bRow) * QP + 16 + bCg) * 2);
        { uint32_t b0[2] = {t4[0], t4[1]}, b1[2] = {t4[2], t4[3]};
          mma16816(acc[2 * nt], a1, b0); mma16816(acc[2 * nt + 1], a1, b1); }
    }

    const int lr = lane >> 2, lc2 = (lane & 3) << 1;
    const int i0 = warp * 16 + lr, i1 = i0 + 8;
    const int pki0 = pk[i0], pki1 = pk[i1];
    const int c1_0 = pki0 >> 16, rg0 = pki0 & 255;
    const int c1_1 = pki1 >> 16, rg1 = pki1 & 255;

    float mx0 = -1e30f, mx1 = -1e30f;
    #pragma unroll
    for (int nb = 0; nb < 8; nb++) {
        #pragma unroll
        for (int jj = 0; jj < 2; jj++) {
            int j = nb * 8 + lc2 + jj;
            int pj = pk[j];
            int c2j = (pj >> 8) & 255, rgj = pj & 255;
            bool jlt = j < L;
            float b0 = bias_s[(c1_0 - c2j) & 255];
            float b1 = bias_s[(c1_1 - c2j) & 255];
            float s0 = acc[nb][jj] + b0 + ((rg0 == rgj) ? 0.f : -100.f);
            float s1 = acc[nb][2 + jj] + b1 + ((rg1 == rgj) ? 0.f : -100.f);
            s0 = jlt ? s0 : -1e30f;
            s1 = jlt ? s1 : -1e30f;
            acc[nb][jj] = s0; acc[nb][2 + jj] = s1;
            mx0 = fmaxf(mx0, s0); mx1 = fmaxf(mx1, s1);
        }
    }
    mx0 = fmaxf(mx0, __shfl_xor_sync(0xffffffffu, mx0, 1));
    mx0 = fmaxf(mx0, __shfl_xor_sync(0xffffffffu, mx0, 2));
    mx1 = fmaxf(mx1, __shfl_xor_sync(0xffffffffu, mx1, 1));
    mx1 = fmaxf(mx1, __shfl_xor_sync(0xffffffffu, mx1, 2));
    float sm0 = 0.f, sm1 = 0.f;
    #pragma unroll
    for (int nb = 0; nb < 8; nb++) {
        #pragma unroll
        for (int jj = 0; jj < 2; jj++) {
            float e0 = __expf(acc[nb][jj] - mx0);
            float e1 = __expf(acc[nb][2 + jj] - mx1);
            acc[nb][jj] = e0; acc[nb][2 + jj] = e1;
            sm0 += e0; sm1 += e1;
        }
    }
    sm0 += __shfl_xor_sync(0xffffffffu, sm0, 1);
    sm0 += __shfl_xor_sync(0xffffffffu, sm0, 2);
    sm1 += __shfl_xor_sync(0xffffffffu, sm1, 1);
    sm1 += __shfl_xor_sync(0xffffffffu, sm1, 2);
    const float inv0 = 1.f / sm0, inv1 = 1.f / sm1;

    // ---- O = P @ V; B-frags straight from row-major V via ldmatrix.trans ----
    float o[4][4];
    #pragma unroll
    for (int i = 0; i < 4; i++)
        #pragma unroll
        for (int j = 0; j < 4; j++) o[i][j] = 0.f;
    #pragma unroll
    for (int ks2 = 0; ks2 < 4; ks2++) {
        uint32_t pa[4];
        __half2 h;
        h = __floats2half2_rn(acc[2 * ks2][0], acc[2 * ks2][1]);         pa[0] = *(uint32_t*)&h;
        h = __floats2half2_rn(acc[2 * ks2][2], acc[2 * ks2][3]);         pa[1] = *(uint32_t*)&h;
        h = __floats2half2_rn(acc[2 * ks2 + 1][0], acc[2 * ks2 + 1][1]); pa[2] = *(uint32_t*)&h;
        h = __floats2half2_rn(acc[2 * ks2 + 1][2], acc[2 * ks2 + 1][3]); pa[3] = *(uint32_t*)&h;
        uint32_t t4[4];
        ldsm4t(t4, vsu + ((ks2 * 16 + aRow) * QP + aCg) * 2);          // d 0-15
        { uint32_t b0[2] = {t4[0], t4[1]}, b1[2] = {t4[2], t4[3]};
          mma16816(o[0], pa, b0); mma16816(o[1], pa, b1); }
        ldsm4t(t4, vsu + ((ks2 * 16 + aRow) * QP + 16 + aCg) * 2);     // d 16-31
        { uint32_t b0[2] = {t4[0], t4[1]}, b1[2] = {t4[2], t4[3]};
          mma16816(o[2], pa, b0); mma16816(o[3], pa, b1); }
    }

    __half* dst = g_att + (size_t)w * L * Cc + head * HD;
    if (i0 < L) {
        #pragma unroll
        for (int nbo = 0; nbo < 4; nbo++) {
            int col = nbo * 8 + lc2;
            __half2 hv = __floats2half2_rn(o[nbo][0] * inv0, o[nbo][1] * inv0);
            *(__half2*)(dst + (size_t)i0 * Cc + col) = hv;
        }
    }
    if (i1 < L) {
        #pragma unroll
        for (int nbo = 0; nbo < 4; nbo++) {
            int col = nbo * 8 + lc2;
            __half2 hv = __floats2half2_rn(o[nbo][2] * inv1, o[nbo][3] * inv1);
            *(__half2*)(dst + (size_t)i1 * Cc + col) = hv;
        }
    }
}

// ---------------- launch ----------------
extern "C" void kernel_launch(void* const* d_in, const int* in_sizes, int n_in,
                              void* d_out, int out_size) {
    const float* x      = (const float*)d_in[0];
    const float* n1w    = (const float*)d_in[1];
    const float* n1b    = (const float*)d_in[2];
    const float* qkv_w  = (const float*)d_in[3];
    const float* qkv_b  = (const float*)d_in[4];
    const float* proj_w = (const float*)d_in[5];
    const float* proj_b = (const float*)d_in[6];
    const float* rel_b  = (const float*)d_in[7];
    const float* n2w    = (const float*)d_in[8];
    const float* n2b    = (const float*)d_in[9];
    const float* fc1_w  = (const float*)d_in[10];
    const float* fc1_b  = (const float*)d_in[11];
    const float* fc2_w  = (const float*)d_in[12];
    const float* fc2_b  = (const float*)d_in[13];
    float* out = (float*)d_out;

    __half *p_att, *p_proj, *p_wproj, *p_wfc1, *p_wfc2;
    cudaGetSymbolAddress((void**)&p_att,  g_att);
    cudaGetSymbolAddress((void**)&p_proj, g_proj);
    cudaGetSymbolAddress((void**)&p_wproj, g_wproj);
    cudaGetSymbolAddress((void**)&p_wfc1, g_wfc1);
    cudaGetSymbolAddress((void**)&p_wfc2, g_wfc2);

    constexpr int SMB = 2 * 128 * LDS * 2;      // 69632 B (k_hmma)
    constexpr int SMB_Q = 320 * LDS * 2;        // 87040 B (k_qkv64, occ 2)
    constexpr int SMB_M = 384 * LDS * 2;        // 104448 B (k_mlp64, occ 2)
    cudaFuncSetAttribute(k_qkv64, cudaFuncAttributeMaxDynamicSharedMemorySize, SMB_Q);
    cudaFuncSetAttribute(k_hmma<128, 128, 0>, cudaFuncAttributeMaxDynamicSharedMemorySize, SMB);
    cudaFuncSetAttribute(k_mlp64, cudaFuncAttributeMaxDynamicSharedMemorySize, SMB_M);

    const int GM = MT / 128;  // 1568 M-tiles

    k_cvt<<<256, 256>>>(qkv_w, proj_w, fc1_w, fc2_w);
    k_qkv64<<<MT / 64, 256, SMB_Q>>>(x, n1w, n1b, qkv_b);
    k_attn<<<dim3(Bz * NW, NH), 128>>>(rel_b);
    k_hmma<128, 128, 0><<<dim3(GM, 1), 256, SMB>>>(p_att, p_wproj, proj_b);
    k_mlp64<<<MT / 64, 256, SMB_M>>>(x, p_proj, p_wfc1, p_wfc2, fc1_b, fc2_b, n2w, n2b, out);
}